// round 6
// baseline (speedup 1.0000x reference)
#include <cuda_runtime.h>
#include <math.h>
#include <stdint.h>

#define Bn 32768
#define Tn 16

// smem word offsets for fused kernel
#define BBUF 0        // 2 x 16384
#define APS  32768    // 2 x 2048
#define H1O  36864    // 4 blocks x 2048 (64 rows x 32 k, swizzled)
#define H2O  45056    // 4 blocks x 2048
#define B1S  53248    // 512
#define B2S  53760    // 512
#define HWS  54272    // 1152
#define SMW  55424
#define SMEM_FUSED_BYTES (SMW * 4)

// ---------------- device scratch ----------------
__device__ float  g_feat[Bn * 128];
__device__ float2 g_c1[512 * 16 * 512];
__device__ float2 g_c2[512 * 16 * 512];
__device__ float  g_W1p[12 * 16384];  // fragment-ordered, gate-interleaved, tf32
__device__ float  g_W2p[8 * 16384];
__device__ float  g_b1[512];          // gate-interleaved order n' = 4j+gate
__device__ float  g_b2[512];

// ---------------- helpers ----------------
__device__ __forceinline__ uint32_t smem_u32(const void* p) {
    uint32_t r;
    asm("{ .reg .u64 t; cvta.to.shared.u64 t, %1; cvt.u32.u64 %0, t; }" : "=r"(r) : "l"(p));
    return r;
}
#define CP16(dst, src) asm volatile("cp.async.cg.shared.global [%0], [%1], 16;" :: "r"(dst), "l"(src))
#define CP_COMMIT()    asm volatile("cp.async.commit_group;" ::: "memory")
#define CP_WAIT0()     asm volatile("cp.async.wait_group 0;" ::: "memory")

#define MMA_TF32(d, a, b0v, b1v) \
    asm volatile("mma.sync.aligned.m16n8k8.row.col.f32.tf32.tf32.f32 " \
        "{%0,%1,%2,%3}, {%4,%5,%6,%7}, {%8,%9}, {%0,%1,%2,%3};" \
        : "+f"((d)[0]), "+f"((d)[1]), "+f"((d)[2]), "+f"((d)[3]) \
        : "r"((a)[0]), "r"((a)[1]), "r"((a)[2]), "r"((a)[3]), "r"(b0v), "r"(b1v))

__device__ __forceinline__ float to_tf32(float x) {
    uint32_t u;
    asm("cvt.rna.tf32.f32 %0, %1;" : "=r"(u) : "f"(x));
    return __uint_as_float(u);
}
__device__ __forceinline__ float sigf(float x) { return __fdividef(1.0f, 1.0f + __expf(-x)); }
__device__ __forceinline__ float tanhx(float x) { return __fdividef(2.0f, 1.0f + __expf(-2.0f * x)) - 1.0f; }
__device__ __forceinline__ float eluf(float x) { return x > 0.0f ? x : expm1f(x); }

// ---------------- weight prep: fragment order + gate interleave + tf32 ----------------
// per layer li = [ch][wn<8][s<4][j4<4][lane<32][w<4]
// k = ch*32 + s*8 + t4 + 4*(w&1); n' = wn*64 + g + 8*(2*j4 + (w>>1))
// gate-interleave: gate = n'&3, j = n'>>2, n_orig = gate*128 + j
__global__ void prep_kernel(const float* __restrict__ w_ih1, const float* __restrict__ w_hh1,
                            const float* __restrict__ b_ih1, const float* __restrict__ b_hh1,
                            const float* __restrict__ w_ih2, const float* __restrict__ w_hh2,
                            const float* __restrict__ b_ih2, const float* __restrict__ b_hh2) {
    int i = blockIdx.x * blockDim.x + threadIdx.x;
    const int total1 = 12 * 16384;
    const int total2 = 8 * 16384;
    if (i < total1 + total2) {
        int li = (i < total1) ? i : i - total1;
        int w    = li & 3;
        int lane = (li >> 2) & 31;
        int j4   = (li >> 7) & 3;
        int s    = (li >> 9) & 3;
        int wn   = (li >> 11) & 7;
        int ch   = li >> 14;
        int g = lane >> 2, t4 = lane & 3;
        int k  = ch * 32 + s * 8 + t4 + 4 * (w & 1);
        int np = wn * 64 + g + 8 * (2 * j4 + (w >> 1));
        int gate = np & 3, j = np >> 2;
        int n_orig = gate * 128 + j;
        float v;
        if (i < total1) {
            v = (k < 256) ? w_ih1[n_orig * 256 + k] : w_hh1[n_orig * 128 + (k - 256)];
            g_W1p[li] = to_tf32(v);
        } else {
            v = (k < 128) ? w_ih2[n_orig * 128 + k] : w_hh2[n_orig * 128 + (k - 128)];
            g_W2p[li] = to_tf32(v);
        }
    } else if (i < total1 + total2 + 512) {
        int np = i - total1 - total2;
        int gate = np & 3, j = np >> 2;
        int n_orig = gate * 128 + j;
        g_b1[np] = b_ih1[n_orig] + b_hh1[n_orig];
    } else if (i < total1 + total2 + 1024) {
        int np = i - total1 - total2 - 512;
        int gate = np & 3, j = np >> 2;
        int n_orig = gate * 128 + j;
        g_b2[np] = b_ih2[n_orig] + b_hh2[n_orig];
    }
}

// ---------------- fused conv stack: x[B,1,19] -> feat[B,128] ----------------
__launch_bounds__(256)
__global__ void conv_kernel(const float* __restrict__ x,
                            const float* __restrict__ w1, const float* __restrict__ b1,
                            const float* __restrict__ w2, const float* __restrict__ b2,
                            const float* __restrict__ w3, const float* __restrict__ b3) {
    extern __shared__ float sm[];
    float* xs  = sm;                 // 304
    float* y1s = xs + 304;           // 6656
    float* y2s = y1s + 6656;         // 7168
    float* w1s = y2s + 7168;         // 224
    float* w2s = w1s + 224;          // 14400
    float* w3c = w2s + 14400;        // 8256

    const int t  = threadIdx.x;
    const int b0 = blockIdx.x * 16;

    for (int idx = t; idx < 16 * 19; idx += 256) xs[idx] = x[b0 * 19 + idx];
    for (int idx = t; idx < 224; idx += 256)     w1s[idx] = w1[idx];
    for (int idx = t; idx < 64 * 224; idx += 256) {
        int co = idx / 224, i = idx - co * 224;
        w2s[co * 225 + i] = w2[idx];
    }
    __syncthreads();

    for (int idx = t; idx < 16 * 416; idx += 256) {
        int b = idx / 416, rem = idx - b * 416;
        int co = rem / 13, p = rem - co * 13;
        float s = b1[co];
#pragma unroll
        for (int k = 0; k < 7; k++) s += xs[b * 19 + p + k] * w1s[co * 7 + k];
        y1s[idx] = eluf(s);
    }
    __syncthreads();

    for (int u = t; u < 448; u += 256) {
        int p = u % 7;
        int cog = (u / 7) & 15;
        int bg = u / 112;
        int bb0 = bg * 4, co0 = cog * 4;
        float acc[4][4];
#pragma unroll
        for (int a = 0; a < 4; a++)
#pragma unroll
            for (int c = 0; c < 4; c++) acc[a][c] = 0.0f;
        for (int ci = 0; ci < 32; ci++) {
            float yv[4][7];
#pragma unroll
            for (int a = 0; a < 4; a++)
#pragma unroll
                for (int k = 0; k < 7; k++)
                    yv[a][k] = y1s[(bb0 + a) * 416 + ci * 13 + p + k];
#pragma unroll
            for (int c = 0; c < 4; c++)
#pragma unroll
                for (int k = 0; k < 7; k++) {
                    float wv = w2s[(co0 + c) * 225 + ci * 7 + k];
#pragma unroll
                    for (int a = 0; a < 4; a++) acc[a][c] += yv[a][k] * wv;
                }
        }
#pragma unroll
        for (int a = 0; a < 4; a++)
#pragma unroll
            for (int c = 0; c < 4; c++) {
                float s = acc[a][c] + b2[co0 + c];
                y2s[(bb0 + a) * 448 + (co0 + c) * 7 + p] = eluf(s);
            }
    }

    const int co0 = (t & 31) * 4;
    const int bb0 = (t >> 5) * 2;
    float acc3[2][4];
#pragma unroll
    for (int a = 0; a < 2; a++)
#pragma unroll
        for (int c = 0; c < 4; c++) acc3[a][c] = 0.0f;

    for (int ch = 0; ch < 7; ch++) {
        int ic = ch * 64;
        __syncthreads();
        for (int idx = t; idx < 8192; idx += 256) {
            int co = idx >> 6, ii = idx & 63;
            w3c[ii * 129 + co] = w3[co * 448 + ic + ii];
        }
        __syncthreads();
#pragma unroll 4
        for (int ii = 0; ii < 64; ii++) {
            float wv0 = w3c[ii * 129 + co0 + 0];
            float wv1 = w3c[ii * 129 + co0 + 1];
            float wv2 = w3c[ii * 129 + co0 + 2];
            float wv3 = w3c[ii * 129 + co0 + 3];
#pragma unroll
            for (int a = 0; a < 2; a++) {
                float yv = y2s[(bb0 + a) * 448 + ic + ii];
                acc3[a][0] += yv * wv0;
                acc3[a][1] += yv * wv1;
                acc3[a][2] += yv * wv2;
                acc3[a][3] += yv * wv3;
            }
        }
    }
#pragma unroll
    for (int a = 0; a < 2; a++)
#pragma unroll
        for (int c = 0; c < 4; c++) {
            float s = acc3[a][c] + b3[co0 + c];
            g_feat[(size_t)(b0 + bb0 + a) * 128 + co0 + c] = eluf(s);
        }
}

// ---------------- fused persistent LSTM kernel ----------------
__device__ __forceinline__ void issue_B(uint32_t smb, int buf, const float* __restrict__ wsrc, int tid) {
    uint32_t bbase = smb + (uint32_t)buf * 65536u;
#pragma unroll
    for (int it = 0; it < 8; it++) {
        int gi = it * 512 + tid;
        CP16(bbase + (uint32_t)gi * 16u, wsrc + (size_t)gi * 4);
    }
}
__device__ __forceinline__ void issue_A(uint32_t smb, int buf, const float* __restrict__ asrc,
                                        int lda, int tid) {
    int r = tid >> 3, q = tid & 7;
    uint32_t word = APS + (uint32_t)buf * 2048u + (uint32_t)(r * 32) +
                    (uint32_t)((4 * q) ^ (4 * (r & 7)));
    CP16(smb + word * 4u, asrc + (size_t)r * lda + q * 4);
}

__device__ __forceinline__ void gemm_run(
    float acc[2][8][4], int nch, int apsN,
    const float* __restrict__ Wstream,
    const float* __restrict__ Asrc, int lda,
    const float* __restrict__ nextW,
    const float* __restrict__ nextA, int nlda,
    const float* sm, uint32_t smb,
    int tid, int wm, int wn, int g, int t4)
{
#pragma unroll
    for (int mt = 0; mt < 2; mt++)
#pragma unroll
        for (int j8 = 0; j8 < 8; j8++)
#pragma unroll
            for (int q = 0; q < 4; q++) acc[mt][j8][q] = 0.0f;

    const int lane = g * 4 + t4;
    for (int i = 0; i < nch; i++) {
        CP_WAIT0();
        __syncthreads();
        int nx = i + 1;
        if (nx < nch) {
            issue_B(smb, nx & 1, Wstream + (size_t)nx * 16384, tid);
            if (nx < apsN) issue_A(smb, nx & 1, Asrc + nx * 32, lda, tid);
            CP_COMMIT();
        } else if (nextW) {
            issue_B(smb, 0, nextW, tid);
            if (nextA) issue_A(smb, 0, nextA, nlda, tid);
            CP_COMMIT();
        }

        const float*  Ab = sm + ((i < apsN) ? (APS + (i & 1) * 2048) : (H1O + (i - apsN) * 2048));
        const float4* Bq = (const float4*)(sm + (i & 1) * 16384 + wn * 2048);

#pragma unroll
        for (int s = 0; s < 4; s++) {
            float4 bv[4];
#pragma unroll
            for (int j4 = 0; j4 < 4; j4++) bv[j4] = Bq[(s * 4 + j4) * 32 + lane];
            uint32_t a[2][4];
#pragma unroll
            for (int mt = 0; mt < 2; mt++) {
                int r0 = wm * 32 + mt * 16 + g;
                int kw0 = (8 * s + t4) ^ (4 * g);
                int kw1 = (8 * s + t4 + 4) ^ (4 * g);
                a[mt][0] = __float_as_uint(Ab[r0 * 32 + kw0]);
                a[mt][1] = __float_as_uint(Ab[(r0 + 8) * 32 + kw0]);
                a[mt][2] = __float_as_uint(Ab[r0 * 32 + kw1]);
                a[mt][3] = __float_as_uint(Ab[(r0 + 8) * 32 + kw1]);
            }
#pragma unroll
            for (int j4 = 0; j4 < 4; j4++) {
                uint32_t b0e = __float_as_uint(bv[j4].x);
                uint32_t b1e = __float_as_uint(bv[j4].y);
                uint32_t b0o = __float_as_uint(bv[j4].z);
                uint32_t b1o = __float_as_uint(bv[j4].w);
                MMA_TF32(acc[0][2 * j4],     a[0], b0e, b1e);
                MMA_TF32(acc[1][2 * j4],     a[1], b0e, b1e);
                MMA_TF32(acc[0][2 * j4 + 1], a[0], b0o, b1o);
                MMA_TF32(acc[1][2 * j4 + 1], a[1], b0o, b1o);
            }
        }
    }
}

// LSTM-cell epilogue via lane-pair shuffles. Gate-interleaved cols: n' = 4j+gate.
__device__ __forceinline__ void epilogue(
    float acc[2][8][4], const float* __restrict__ bias_s,
    float* sm, int hoff, float2* __restrict__ cbase, bool cold,
    int tid, int wm, int wn, int g, int t4)
{
    const bool evn = (t4 & 1) == 0;
#pragma unroll
    for (int mt = 0; mt < 2; mt++) {
#pragma unroll
        for (int j8 = 0; j8 < 8; j8++) {
            int n0 = wn * 64 + j8 * 8 + 2 * t4;
            float v0 = acc[mt][j8][0] + bias_s[n0];
            float v1 = acc[mt][j8][1] + bias_s[n0 + 1];
            float v2 = acc[mt][j8][2] + bias_s[n0];
            float v3 = acc[mt][j8][3] + bias_s[n0 + 1];
            float e0 = evn ? sigf(v0) : tanhx(v0);
            float e1 = sigf(v1);
            float e2 = evn ? sigf(v2) : tanhx(v2);
            float e3 = sigf(v3);
            float si0 = __shfl_xor_sync(0xFFFFFFFFu, e0, 1);
            float sf0 = __shfl_xor_sync(0xFFFFFFFFu, e1, 1);
            float si8 = __shfl_xor_sync(0xFFFFFFFFu, e2, 1);
            float sf8 = __shfl_xor_sync(0xFFFFFFFFu, e3, 1);
            if (!evn) {
                int q2 = mt * 8 + j8;
                float2 cp = cold ? make_float2(0.0f, 0.0f) : cbase[q2 * 512 + tid];
                float c0 = sf0 * cp.x + si0 * e0;
                float c8 = sf8 * cp.y + si8 * e2;
                cbase[q2 * 512 + tid] = make_float2(c0, c8);
                float h0 = e1 * tanhx(c0);
                float h8 = e3 * tanhx(c8);
                int j = wn * 16 + j8 * 2 + (t4 >> 1);
                int r = wm * 32 + mt * 16 + g;
                int base = hoff + (j >> 5) * 2048 + ((j & 31) ^ (4 * g));
                sm[base + r * 32] = h0;
                sm[base + (r + 8) * 32] = h8;
            }
        }
    }
}

__device__ __forceinline__ void head_out(
    const float* sm, const float* __restrict__ headB,
    float* __restrict__ outp, int tid)
{
    for (int idx = tid; idx < 576; idx += 512) {
        int r = idx / 9, o = idx - r * 9;
        float s = headB[o];
        int rbase = r * 32;
        int rx = 4 * (r & 7);
#pragma unroll 8
        for (int jj = 0; jj < 128; jj++) {
            float hv = sm[H2O + (jj >> 5) * 2048 + rbase + ((jj & 31) ^ rx)];
            s += hv * sm[HWS + jj * 9 + o];
        }
        outp[(size_t)r * 9 + o] = s;
    }
}

__global__ __launch_bounds__(512, 1)
void fused_lstm_kernel(const float* __restrict__ ps,
                       const float* __restrict__ headW,
                       const float* __restrict__ headB,
                       float* __restrict__ out)
{
    extern __shared__ float sm[];
    uint32_t smb = smem_u32(sm);

    const int tid  = threadIdx.x;
    const int wid  = tid >> 5;
    const int lane = tid & 31;
    const int g    = lane >> 2;
    const int t4   = lane & 3;
    const int wm   = wid & 1;
    const int wn   = wid >> 1;
    const int cta  = blockIdx.x;
    const int row0 = cta * 64;

    sm[B1S + tid] = g_b1[tid];
    sm[B2S + tid] = g_b2[tid];
    for (int i = tid; i < 1152; i += 512) {
        int j = i / 9, o = i - j * 9;
        sm[HWS + i] = headW[o * 128 + j];
    }
    __syncthreads();

    float2* c1b = g_c1 + (size_t)cta * 16 * 512;
    float2* c2b = g_c2 + (size_t)cta * 16 * 512;
    const float* featp = g_feat + (size_t)row0 * 128;
    const float* psb   = ps + (size_t)row0 * 256;

    float acc[2][8][4];

    // prologue: step0 L1 chunk0
    issue_B(smb, 0, g_W1p, tid);
    issue_A(smb, 0, featp, 128, tid);
    CP_COMMIT();

    // ---- step 0 ----
    gemm_run(acc, 4, 4, g_W1p, featp, 128, g_W2p, nullptr, 0, sm, smb, tid, wm, wn, g, t4);
    __syncthreads();
    epilogue(acc, sm + B1S, sm, H1O, c1b, true, tid, wm, wn, g, t4);
    __syncthreads();
    gemm_run(acc, 4, 0, g_W2p, nullptr, 0, g_W1p, psb, 256, sm, smb, tid, wm, wn, g, t4);
    __syncthreads();
    epilogue(acc, sm + B2S, sm, H2O, c2b, true, tid, wm, wn, g, t4);
    __syncthreads();
    head_out(sm, headB, out + (size_t)row0 * 9, tid);

    // ---- steps 1..16 ----
    for (int st = 1; st <= Tn; st++) {
        const float* A = psb + (size_t)(st - 1) * Bn * 256;
        gemm_run(acc, 12, 8, g_W1p, A, 256, g_W2p, nullptr, 0, sm, smb, tid, wm, wn, g, t4);
        __syncthreads();
        epilogue(acc, sm + B1S, sm, H1O, c1b, false, tid, wm, wn, g, t4);
        __syncthreads();
        const float* nW = (st < Tn) ? g_W1p : nullptr;
        const float* nA = (st < Tn) ? (psb + (size_t)st * Bn * 256) : nullptr;
        gemm_run(acc, 8, 0, g_W2p, nullptr, 0, nW, nA, 256, sm, smb, tid, wm, wn, g, t4);
        __syncthreads();
        epilogue(acc, sm + B2S, sm, H2O, c2b, false, tid, wm, wn, g, t4);
        __syncthreads();
        head_out(sm, headB, out + ((size_t)st * Bn + row0) * 9, tid);
    }
}

// ---------------- launch ----------------
extern "C" void kernel_launch(void* const* d_in, const int* in_sizes, int n_in,
                              void* d_out, int out_size) {
    const float* x        = (const float*)d_in[0];
    const float* ps       = (const float*)d_in[1];
    const float* conv1_w  = (const float*)d_in[2];
    const float* conv1_b  = (const float*)d_in[3];
    const float* conv2_w  = (const float*)d_in[4];
    const float* conv2_b  = (const float*)d_in[5];
    const float* conv3_w  = (const float*)d_in[6];
    const float* conv3_b  = (const float*)d_in[7];
    const float* w_ih1    = (const float*)d_in[8];
    const float* w_hh1    = (const float*)d_in[9];
    const float* b_ih1    = (const float*)d_in[10];
    const float* b_hh1    = (const float*)d_in[11];
    const float* w_ih2    = (const float*)d_in[12];
    const float* w_hh2    = (const float*)d_in[13];
    const float* b_ih2    = (const float*)d_in[14];
    const float* b_hh2    = (const float*)d_in[15];
    const float* head_w   = (const float*)d_in[16];
    const float* head_b   = (const float*)d_in[17];
    float* out = (float*)d_out;

    const int conv_smem = 37008 * 4;
    cudaFuncSetAttribute(conv_kernel, cudaFuncAttributeMaxDynamicSharedMemorySize, conv_smem);
    cudaFuncSetAttribute(fused_lstm_kernel, cudaFuncAttributeMaxDynamicSharedMemorySize, SMEM_FUSED_BYTES);

    const int prep_total = 12 * 16384 + 8 * 16384 + 1024;
    prep_kernel<<<(prep_total + 255) / 256, 256>>>(w_ih1, w_hh1, b_ih1, b_hh1,
                                                   w_ih2, w_hh2, b_ih2, b_hh2);

    conv_kernel<<<Bn / 16, 256, conv_smem>>>(x, conv1_w, conv1_b, conv2_w, conv2_b,
                                             conv3_w, conv3_b);

    fused_lstm_kernel<<<512, 512, SMEM_FUSED_BYTES>>>(ps, head_w, head_b, out);
}

// round 7
// speedup vs baseline: 1.4085x; 1.4085x over previous
#include <cuda_runtime.h>
#include <cuda_fp16.h>
#include <math.h>
#include <stdint.h>

#define Bn 32768
#define Tn 16

// ---------------- device scratch ----------------
__device__ float    g_feat[Bn * 128];
__device__ float    g_h1[Bn * 128];
__device__ float    g_c1[Bn * 128];
__device__ float    g_h2[Bn * 128];
__device__ float    g_c2[Bn * 128];
__device__ uint32_t g_W1h[12 * 8192];   // fragment-ordered half2 words
__device__ uint32_t g_W2h[8 * 8192];
__device__ float    g_b1[512];
__device__ float    g_b2[512];

// ---------------- helpers ----------------
__device__ __forceinline__ uint32_t smem_u32(const void* p) {
    uint32_t r;
    asm("{ .reg .u64 t; cvta.to.shared.u64 t, %1; cvt.u32.u64 %0, t; }" : "=r"(r) : "l"(p));
    return r;
}
#define CP16(dst, src) asm volatile("cp.async.cg.shared.global [%0], [%1], 16;" :: "r"(dst), "l"(src))
#define CP_COMMIT()    asm volatile("cp.async.commit_group;" ::: "memory")
#define CP_WAIT0()     asm volatile("cp.async.wait_group 0;" ::: "memory")
#define CP_WAIT1()     asm volatile("cp.async.wait_group 1;" ::: "memory")

#define MMA_F16(d, a, b0v, b1v) \
    asm volatile("mma.sync.aligned.m16n8k16.row.col.f32.f16.f16.f32 " \
        "{%0,%1,%2,%3}, {%4,%5,%6,%7}, {%8,%9}, {%0,%1,%2,%3};" \
        : "+f"((d)[0]), "+f"((d)[1]), "+f"((d)[2]), "+f"((d)[3]) \
        : "r"((a)[0]), "r"((a)[1]), "r"((a)[2]), "r"((a)[3]), "r"(b0v), "r"(b1v))

__device__ __forceinline__ uint32_t pack_h2(float lo, float hi) {
    __half2 h = __floats2half2_rn(lo, hi);
    uint32_t u;
    memcpy(&u, &h, 4);
    return u;
}
__device__ __forceinline__ float sigf(float x) { return __fdividef(1.0f, 1.0f + __expf(-x)); }
__device__ __forceinline__ float tanhx(float x) { return __fdividef(2.0f, 1.0f + __expf(-2.0f * x)) - 1.0f; }
__device__ __forceinline__ float eluf(float x) { return x > 0.0f ? x : expm1f(x); }

// ---------------- weight prep: fragment-ordered half2 packing + bias fuse ----------------
// li = [ch][wn<8][s<2][jp<4][lane<32][w<4]; per chunk 8192 words.
// j8 = 2*jp + (w>>1); k = ch*32 + s*16 + 8*(w&1) + 2*t4 (even); n = wn*64 + j8*8 + g.
__global__ void prep_kernel(const float* __restrict__ w_ih1, const float* __restrict__ w_hh1,
                            const float* __restrict__ b_ih1, const float* __restrict__ b_hh1,
                            const float* __restrict__ w_ih2, const float* __restrict__ w_hh2,
                            const float* __restrict__ b_ih2, const float* __restrict__ b_hh2) {
    int i = blockIdx.x * blockDim.x + threadIdx.x;
    const int total1 = 12 * 8192;
    const int total2 = 8 * 8192;
    if (i < total1 + total2) {
        int li = (i < total1) ? i : i - total1;
        int w    = li & 3;
        int lane = (li >> 2) & 31;
        int jp   = (li >> 7) & 3;
        int s    = (li >> 9) & 1;
        int wn   = (li >> 10) & 7;
        int ch   = li >> 13;
        int g = lane >> 2, t4 = lane & 3;
        int j8 = jp * 2 + (w >> 1);
        int k = ch * 32 + s * 16 + 8 * (w & 1) + 2 * t4;
        int n = wn * 64 + j8 * 8 + g;
        float f0, f1;
        if (i < total1) {
            if (k < 256) { f0 = w_ih1[n * 256 + k];        f1 = w_ih1[n * 256 + k + 1]; }
            else         { f0 = w_hh1[n * 128 + k - 256];  f1 = w_hh1[n * 128 + k - 255]; }
            g_W1h[li] = pack_h2(f0, f1);
        } else {
            if (k < 128) { f0 = w_ih2[n * 128 + k];        f1 = w_ih2[n * 128 + k + 1]; }
            else         { f0 = w_hh2[n * 128 + k - 128];  f1 = w_hh2[n * 128 + k - 127]; }
            g_W2h[li] = pack_h2(f0, f1);
        }
    } else if (i < total1 + total2 + 512) {
        int n = i - total1 - total2;
        g_b1[n] = b_ih1[n] + b_hh1[n];
    } else if (i < total1 + total2 + 1024) {
        int n = i - total1 - total2 - 512;
        g_b2[n] = b_ih2[n] + b_hh2[n];
    }
}

// ---------------- fused conv stack: x[B,1,19] -> feat[B,128] ----------------
__launch_bounds__(256)
__global__ void conv_kernel(const float* __restrict__ x,
                            const float* __restrict__ w1, const float* __restrict__ b1,
                            const float* __restrict__ w2, const float* __restrict__ b2,
                            const float* __restrict__ w3, const float* __restrict__ b3) {
    extern __shared__ float sm[];
    float* xs  = sm;                 // 304
    float* y1s = xs + 304;           // 6656
    float* y2s = y1s + 6656;         // 7168
    float* w1s = y2s + 7168;         // 224
    float* w2s = w1s + 224;          // 14400
    float* w3c = w2s + 14400;        // 8256

    const int t  = threadIdx.x;
    const int b0 = blockIdx.x * 16;

    for (int idx = t; idx < 16 * 19; idx += 256) xs[idx] = x[b0 * 19 + idx];
    for (int idx = t; idx < 224; idx += 256)     w1s[idx] = w1[idx];
    for (int idx = t; idx < 64 * 224; idx += 256) {
        int co = idx / 224, i = idx - co * 224;
        w2s[co * 225 + i] = w2[idx];
    }
    __syncthreads();

    for (int idx = t; idx < 16 * 416; idx += 256) {
        int b = idx / 416, rem = idx - b * 416;
        int co = rem / 13, p = rem - co * 13;
        float s = b1[co];
#pragma unroll
        for (int k = 0; k < 7; k++) s += xs[b * 19 + p + k] * w1s[co * 7 + k];
        y1s[idx] = eluf(s);
    }
    __syncthreads();

    for (int u = t; u < 448; u += 256) {
        int p = u % 7;
        int cog = (u / 7) & 15;
        int bg = u / 112;
        int bb0 = bg * 4, co0 = cog * 4;
        float acc[4][4];
#pragma unroll
        for (int a = 0; a < 4; a++)
#pragma unroll
            for (int c = 0; c < 4; c++) acc[a][c] = 0.0f;
        for (int ci = 0; ci < 32; ci++) {
            float yv[4][7];
#pragma unroll
            for (int a = 0; a < 4; a++)
#pragma unroll
                for (int k = 0; k < 7; k++)
                    yv[a][k] = y1s[(bb0 + a) * 416 + ci * 13 + p + k];
#pragma unroll
            for (int c = 0; c < 4; c++)
#pragma unroll
                for (int k = 0; k < 7; k++) {
                    float wv = w2s[(co0 + c) * 225 + ci * 7 + k];
#pragma unroll
                    for (int a = 0; a < 4; a++) acc[a][c] += yv[a][k] * wv;
                }
        }
#pragma unroll
        for (int a = 0; a < 4; a++)
#pragma unroll
            for (int c = 0; c < 4; c++) {
                float s = acc[a][c] + b2[co0 + c];
                y2s[(bb0 + a) * 448 + (co0 + c) * 7 + p] = eluf(s);
            }
    }

    const int co0 = (t & 31) * 4;
    const int bb0 = (t >> 5) * 2;
    float acc3[2][4];
#pragma unroll
    for (int a = 0; a < 2; a++)
#pragma unroll
        for (int c = 0; c < 4; c++) acc3[a][c] = 0.0f;

    for (int ch = 0; ch < 7; ch++) {
        int ic = ch * 64;
        __syncthreads();
        for (int idx = t; idx < 8192; idx += 256) {
            int co = idx >> 6, ii = idx & 63;
            w3c[ii * 129 + co] = w3[co * 448 + ic + ii];
        }
        __syncthreads();
#pragma unroll 4
        for (int ii = 0; ii < 64; ii++) {
            float wv0 = w3c[ii * 129 + co0 + 0];
            float wv1 = w3c[ii * 129 + co0 + 1];
            float wv2 = w3c[ii * 129 + co0 + 2];
            float wv3 = w3c[ii * 129 + co0 + 3];
#pragma unroll
            for (int a = 0; a < 2; a++) {
                float yv = y2s[(bb0 + a) * 448 + ic + ii];
                acc3[a][0] += yv * wv0;
                acc3[a][1] += yv * wv1;
                acc3[a][2] += yv * wv2;
                acc3[a][3] += yv * wv3;
            }
        }
    }
#pragma unroll
    for (int a = 0; a < 2; a++)
#pragma unroll
        for (int c = 0; c < 4; c++) {
            float s = acc3[a][c] + b3[co0 + c];
            g_feat[(size_t)(b0 + bb0 + a) * 128 + co0 + c] = eluf(s);
        }
}

// ---------------- fp16 mma.sync LSTM-cell GEMM ----------------
// SMEM words: B ring 3x8192 @0, A ring 3x1024 @24576 (half2 words, swizzled),
// gate staging [64][516] reuses 0..33023, bias @33024, hw @33536. Total 34688.
#define SMEM_GEMM_WORDS 34688
#define SMEM_GEMM_BYTES (SMEM_GEMM_WORDS * 4)
#define AOFF 24576

__global__ __launch_bounds__(512, 1)
void lstm_mma_kernel(const float* __restrict__ A0, int lda0, int k0len,
                     const float* __restrict__ A1, int lda1, int k1len,
                     const uint32_t* __restrict__ Wp,
                     const float* __restrict__ bias,
                     const float* __restrict__ Cprev,
                     float* __restrict__ Hout, float* __restrict__ Cout,
                     const float* __restrict__ headW, const float* __restrict__ headB,
                     float* __restrict__ logits)
{
    extern __shared__ float sm[];
    uint32_t* smw = (uint32_t*)sm;
    float* bias_s = sm + 33024;
    float* hw_s   = sm + 33536;
    uint32_t smb = smem_u32(sm);

    const int tid  = threadIdx.x;
    const int wid  = tid >> 5;
    const int lane = tid & 31;
    const int g    = lane >> 2;
    const int t4   = lane & 3;
    const int wm   = wid & 1;
    const int wn   = wid >> 1;
    const int row0 = blockIdx.x * 64;
    const int ar   = tid >> 3;      // A row this thread loads
    const int aq   = tid & 7;       // A quad (4 floats)

    bias_s[tid] = bias[tid];
    if (logits) {
        for (int idx = tid; idx < 1152; idx += 512) {
            int j = idx / 9, o = idx - j * 9;
            hw_s[idx] = headW[o * 128 + j];
        }
    }
    __syncthreads();

    float acc[2][8][4];
#pragma unroll
    for (int mt = 0; mt < 2; mt++)
#pragma unroll
        for (int j8 = 0; j8 < 8; j8++)
#pragma unroll
            for (int q = 0; q < 4; q++) acc[mt][j8][q] = 0.0f;

    const int nch = (k0len + k1len) >> 5;

    // ---- A load/convert/store helpers ----
    const int awsw = (2 * aq) ^ (2 * (ar & 7));   // swizzled even word-in-row
    auto ldgA = [&](int i) -> float4 {
        int kb = i << 5;
        const float* src; int ld; int col;
        if (kb < k0len) { src = A0; ld = lda0; col = kb; }
        else            { src = A1; ld = lda1; col = kb - k0len; }
        return *(const float4*)(src + (size_t)(row0 + ar) * ld + col + aq * 4);
    };
    auto stsA = [&](int i, float4 v) {
        uint32_t* p = smw + AOFF + (i % 3) * 1024 + ar * 16 + awsw;
        p[0] = pack_h2(v.x, v.y);
        p[1] = pack_h2(v.z, v.w);
    };
    auto issueB = [&](int i) {
        const uint32_t* wsrc = Wp + (size_t)i * 8192;
        uint32_t bbase = smb + (uint32_t)(i % 3) * 32768u;
#pragma unroll
        for (int it = 0; it < 4; it++) {
            int gi = it * 512 + tid;
            CP16(bbase + (uint32_t)gi * 16u, wsrc + (size_t)gi * 4);
        }
        CP_COMMIT();
    };

    // ---- prologue ----
    float4 hold;
    {
        float4 a0v = ldgA(0);
        stsA(0, a0v);
        issueB(0);
        if (nch > 1) { hold = ldgA(1); issueB(1); }
    }

    const int xg = 2 * g;
    for (int i = 0; i < nch; i++) {
        if (i == nch - 1) { CP_WAIT0(); } else { CP_WAIT1(); }
        __syncthreads();
        if (i + 1 < nch) stsA(i + 1, hold);
        if (i + 2 < nch) { hold = ldgA(i + 2); issueB(i + 2); }

        const uint32_t* Aw = smw + AOFF + (i % 3) * 1024;
        const uint4*    Bq = (const uint4*)(smw + (i % 3) * 8192 + wn * 1024);

#pragma unroll
        for (int s = 0; s < 2; s++) {
            uint4 bv[4];
#pragma unroll
            for (int jp = 0; jp < 4; jp++) bv[jp] = Bq[s * 128 + jp * 32 + lane];
            uint32_t a[2][4];
#pragma unroll
            for (int mt = 0; mt < 2; mt++) {
                int r0 = wm * 32 + mt * 16 + g;
                int w0 = (s * 8 + t4) ^ xg;
                int w1 = (s * 8 + 4 + t4) ^ xg;
                a[mt][0] = Aw[r0 * 16 + w0];
                a[mt][1] = Aw[(r0 + 8) * 16 + w0];
                a[mt][2] = Aw[r0 * 16 + w1];
                a[mt][3] = Aw[(r0 + 8) * 16 + w1];
            }
#pragma unroll
            for (int jp = 0; jp < 4; jp++) {
                MMA_F16(acc[0][2 * jp],     a[0], bv[jp].x, bv[jp].y);
                MMA_F16(acc[1][2 * jp],     a[1], bv[jp].x, bv[jp].y);
                MMA_F16(acc[0][2 * jp + 1], a[0], bv[jp].z, bv[jp].w);
                MMA_F16(acc[1][2 * jp + 1], a[1], bv[jp].z, bv[jp].w);
            }
        }
    }
    __syncthreads();

    // ---- stage gates to smem [64][516] (reuses B/A region) ----
#pragma unroll
    for (int mt = 0; mt < 2; mt++) {
        int row = wm * 32 + mt * 16 + g;
#pragma unroll
        for (int j8 = 0; j8 < 8; j8++) {
            int col = wn * 64 + j8 * 8 + 2 * t4;
            sm[row * 516 + col]           = acc[mt][j8][0];
            sm[row * 516 + col + 1]       = acc[mt][j8][1];
            sm[(row + 8) * 516 + col]     = acc[mt][j8][2];
            sm[(row + 8) * 516 + col + 1] = acc[mt][j8][3];
        }
    }
    __syncthreads();

    // ---- LSTM cell epilogue ----
    const int j  = tid & 127;
    const int rg = tid >> 7;
    const float bi = bias_s[j], bf = bias_s[128 + j], bg = bias_s[256 + j], bo = bias_s[384 + j];
#pragma unroll
    for (int rr = 0; rr < 16; rr++) {
        int r = rg * 16 + rr;
        int row = row0 + r;
        float gi = sm[r * 516 + j]       + bi;
        float gf = sm[r * 516 + 128 + j] + bf;
        float gg = sm[r * 516 + 256 + j] + bg;
        float go = sm[r * 516 + 384 + j] + bo;
        float cp = Cprev ? Cprev[(size_t)row * 128 + j] : 0.0f;
        float c  = sigf(gf) * cp + sigf(gi) * tanhx(gg);
        float h  = sigf(go) * tanhx(c);
        Cout[(size_t)row * 128 + j] = c;
        Hout[(size_t)row * 128 + j] = h;
        sm[r * 516 + j] = h;
    }

    if (logits) {
        __syncthreads();
        for (int idx = tid; idx < 576; idx += 512) {
            int r = idx / 9, o = idx - r * 9;
            const float* hr = sm + r * 516;
            float ssum = headB[o];
#pragma unroll 8
            for (int jj = 0; jj < 128; jj++) ssum += hr[jj] * hw_s[jj * 9 + o];
            logits[(size_t)(row0 + r) * 9 + o] = ssum;
        }
    }
}

// ---------------- launch ----------------
extern "C" void kernel_launch(void* const* d_in, const int* in_sizes, int n_in,
                              void* d_out, int out_size) {
    const float* x        = (const float*)d_in[0];
    const float* ps       = (const float*)d_in[1];
    const float* conv1_w  = (const float*)d_in[2];
    const float* conv1_b  = (const float*)d_in[3];
    const float* conv2_w  = (const float*)d_in[4];
    const float* conv2_b  = (const float*)d_in[5];
    const float* conv3_w  = (const float*)d_in[6];
    const float* conv3_b  = (const float*)d_in[7];
    const float* w_ih1    = (const float*)d_in[8];
    const float* w_hh1    = (const float*)d_in[9];
    const float* b_ih1    = (const float*)d_in[10];
    const float* b_hh1    = (const float*)d_in[11];
    const float* w_ih2    = (const float*)d_in[12];
    const float* w_hh2    = (const float*)d_in[13];
    const float* b_ih2    = (const float*)d_in[14];
    const float* b_hh2    = (const float*)d_in[15];
    const float* head_w   = (const float*)d_in[16];
    const float* head_b   = (const float*)d_in[17];
    float* out = (float*)d_out;

    const int conv_smem = 37008 * 4;
    cudaFuncSetAttribute(conv_kernel, cudaFuncAttributeMaxDynamicSharedMemorySize, conv_smem);
    cudaFuncSetAttribute(lstm_mma_kernel, cudaFuncAttributeMaxDynamicSharedMemorySize, SMEM_GEMM_BYTES);

    float *feat, *h1, *c1, *h2, *c2, *b1, *b2;
    uint32_t *W1h, *W2h;
    cudaGetSymbolAddress((void**)&feat, g_feat);
    cudaGetSymbolAddress((void**)&h1, g_h1);
    cudaGetSymbolAddress((void**)&c1, g_c1);
    cudaGetSymbolAddress((void**)&h2, g_h2);
    cudaGetSymbolAddress((void**)&c2, g_c2);
    cudaGetSymbolAddress((void**)&W1h, g_W1h);
    cudaGetSymbolAddress((void**)&W2h, g_W2h);
    cudaGetSymbolAddress((void**)&b1, g_b1);
    cudaGetSymbolAddress((void**)&b2, g_b2);

    const int prep_total = 12 * 8192 + 8 * 8192 + 1024;
    prep_kernel<<<(prep_total + 255) / 256, 256>>>(w_ih1, w_hh1, b_ih1, b_hh1,
                                                   w_ih2, w_hh2, b_ih2, b_hh2);

    conv_kernel<<<Bn / 16, 256, conv_smem>>>(x, conv1_w, conv1_b, conv2_w, conv2_b,
                                             conv3_w, conv3_b);

    const int grid = Bn / 64;
    // step 0: input = [feat, 0], h=c=0; k>=128 contributes nothing for L1
    lstm_mma_kernel<<<grid, 512, SMEM_GEMM_BYTES>>>(
        feat, 128, 128, nullptr, 0, 0, W1h, b1,
        nullptr, h1, c1, head_w, head_b, nullptr);
    lstm_mma_kernel<<<grid, 512, SMEM_GEMM_BYTES>>>(
        h1, 128, 128, nullptr, 0, 0, W2h, b2,
        nullptr, h2, c2, head_w, head_b, out);
    // steps 1..16
    for (int s = 1; s <= Tn; s++) {
        const float* A = ps + (size_t)(s - 1) * Bn * 256;
        lstm_mma_kernel<<<grid, 512, SMEM_GEMM_BYTES>>>(
            A, 256, 256, h1, 128, 128, W1h, b1,
            c1, h1, c1, head_w, head_b, nullptr);
        lstm_mma_kernel<<<grid, 512, SMEM_GEMM_BYTES>>>(
            h1, 128, 128, h2, 128, 128, W2h, b2,
            c2, h2, c2, head_w, head_b, out + (size_t)s * Bn * 9);
    }
}

// round 8
// speedup vs baseline: 1.4109x; 1.0017x over previous
#include <cuda_runtime.h>
#include <cuda_fp16.h>
#include <math.h>
#include <stdint.h>

#define Bn 32768
#define Tn 16

// ---------------- device scratch ----------------
__device__ float    g_feat[Bn * 128];
__device__ float    g_h1[Bn * 128];
__device__ float    g_c1[Bn * 128];
__device__ float    g_h2[Bn * 128];
__device__ float    g_c2[Bn * 128];
__device__ uint32_t g_W1h[12 * 8192];   // fragment-ordered half2 words
__device__ uint32_t g_W2h[8 * 8192];
__device__ float    g_b1[512];
__device__ float    g_b2[512];

// ---------------- helpers ----------------
__device__ __forceinline__ uint32_t smem_u32(const void* p) {
    uint32_t r;
    asm("{ .reg .u64 t; cvta.to.shared.u64 t, %1; cvt.u32.u64 %0, t; }" : "=r"(r) : "l"(p));
    return r;
}
#define CP16(dst, src) asm volatile("cp.async.cg.shared.global [%0], [%1], 16;" :: "r"(dst), "l"(src))
#define CP_COMMIT()    asm volatile("cp.async.commit_group;" ::: "memory")
#define CP_WAIT0()     asm volatile("cp.async.wait_group 0;" ::: "memory")
#define CP_WAIT1()     asm volatile("cp.async.wait_group 1;" ::: "memory")

#define MMA_F16(d, a, b0v, b1v) \
    asm volatile("mma.sync.aligned.m16n8k16.row.col.f32.f16.f16.f32 " \
        "{%0,%1,%2,%3}, {%4,%5,%6,%7}, {%8,%9}, {%0,%1,%2,%3};" \
        : "+f"((d)[0]), "+f"((d)[1]), "+f"((d)[2]), "+f"((d)[3]) \
        : "r"((a)[0]), "r"((a)[1]), "r"((a)[2]), "r"((a)[3]), "r"(b0v), "r"(b1v))

__device__ __forceinline__ uint32_t pack_h2(float lo, float hi) {
    __half2 h = __floats2half2_rn(lo, hi);
    uint32_t u;
    memcpy(&u, &h, 4);
    return u;
}
__device__ __forceinline__ float sigf(float x) { return __fdividef(1.0f, 1.0f + __expf(-x)); }
__device__ __forceinline__ float tanhx(float x) { return __fdividef(2.0f, 1.0f + __expf(-2.0f * x)) - 1.0f; }
__device__ __forceinline__ float eluf(float x) { return x > 0.0f ? x : expm1f(x); }

// ---------------- weight prep: fragment-ordered half2 packing + bias fuse ----------------
// li = [ch][wn<8][s<2][jp<4][lane<32][w<4]; per chunk 8192 words.
// j8 = 2*jp + (w>>1); k = ch*32 + s*16 + 8*(w&1) + 2*t4 (even); n = wn*64 + j8*8 + g.
__global__ void prep_kernel(const float* __restrict__ w_ih1, const float* __restrict__ w_hh1,
                            const float* __restrict__ b_ih1, const float* __restrict__ b_hh1,
                            const float* __restrict__ w_ih2, const float* __restrict__ w_hh2,
                            const float* __restrict__ b_ih2, const float* __restrict__ b_hh2) {
    int i = blockIdx.x * blockDim.x + threadIdx.x;
    const int total1 = 12 * 8192;
    const int total2 = 8 * 8192;
    if (i < total1 + total2) {
        int li = (i < total1) ? i : i - total1;
        int w    = li & 3;
        int lane = (li >> 2) & 31;
        int jp   = (li >> 7) & 3;
        int s    = (li >> 9) & 1;
        int wn   = (li >> 10) & 7;
        int ch   = li >> 13;
        int g = lane >> 2, t4 = lane & 3;
        int j8 = jp * 2 + (w >> 1);
        int k = ch * 32 + s * 16 + 8 * (w & 1) + 2 * t4;
        int n = wn * 64 + j8 * 8 + g;
        float f0, f1;
        if (i < total1) {
            if (k < 256) { f0 = w_ih1[n * 256 + k];        f1 = w_ih1[n * 256 + k + 1]; }
            else         { f0 = w_hh1[n * 128 + k - 256];  f1 = w_hh1[n * 128 + k - 255]; }
            g_W1h[li] = pack_h2(f0, f1);
        } else {
            if (k < 128) { f0 = w_ih2[n * 128 + k];        f1 = w_ih2[n * 128 + k + 1]; }
            else         { f0 = w_hh2[n * 128 + k - 128];  f1 = w_hh2[n * 128 + k - 127]; }
            g_W2h[li] = pack_h2(f0, f1);
        }
    } else if (i < total1 + total2 + 512) {
        int n = i - total1 - total2;
        g_b1[n] = b_ih1[n] + b_hh1[n];
    } else if (i < total1 + total2 + 1024) {
        int n = i - total1 - total2 - 512;
        g_b2[n] = b_ih2[n] + b_hh2[n];
    }
}

// ---------------- fused conv stack: x[B,1,19] -> feat[B,128] ----------------
__launch_bounds__(256)
__global__ void conv_kernel(const float* __restrict__ x,
                            const float* __restrict__ w1, const float* __restrict__ b1,
                            const float* __restrict__ w2, const float* __restrict__ b2,
                            const float* __restrict__ w3, const float* __restrict__ b3) {
    extern __shared__ float sm[];
    float* xs  = sm;                 // 304
    float* y1s = xs + 304;           // 6656
    float* y2s = y1s + 6656;         // 7168
    float* w1s = y2s + 7168;         // 224
    float* w2s = w1s + 224;          // 14400
    float* w3c = w2s + 14400;        // 8256

    const int t  = threadIdx.x;
    const int b0 = blockIdx.x * 16;

    for (int idx = t; idx < 16 * 19; idx += 256) xs[idx] = x[b0 * 19 + idx];
    for (int idx = t; idx < 224; idx += 256)     w1s[idx] = w1[idx];
    for (int idx = t; idx < 64 * 224; idx += 256) {
        int co = idx / 224, i = idx - co * 224;
        w2s[co * 225 + i] = w2[idx];
    }
    __syncthreads();

    for (int idx = t; idx < 16 * 416; idx += 256) {
        int b = idx / 416, rem = idx - b * 416;
        int co = rem / 13, p = rem - co * 13;
        float s = b1[co];
#pragma unroll
        for (int k = 0; k < 7; k++) s += xs[b * 19 + p + k] * w1s[co * 7 + k];
        y1s[idx] = eluf(s);
    }
    __syncthreads();

    for (int u = t; u < 448; u += 256) {
        int p = u % 7;
        int cog = (u / 7) & 15;
        int bg = u / 112;
        int bb0 = bg * 4, co0 = cog * 4;
        float acc[4][4];
#pragma unroll
        for (int a = 0; a < 4; a++)
#pragma unroll
            for (int c = 0; c < 4; c++) acc[a][c] = 0.0f;
        for (int ci = 0; ci < 32; ci++) {
            float yv[4][7];
#pragma unroll
            for (int a = 0; a < 4; a++)
#pragma unroll
                for (int k = 0; k < 7; k++)
                    yv[a][k] = y1s[(bb0 + a) * 416 + ci * 13 + p + k];
#pragma unroll
            for (int c = 0; c < 4; c++)
#pragma unroll
                for (int k = 0; k < 7; k++) {
                    float wv = w2s[(co0 + c) * 225 + ci * 7 + k];
#pragma unroll
                    for (int a = 0; a < 4; a++) acc[a][c] += yv[a][k] * wv;
                }
        }
#pragma unroll
        for (int a = 0; a < 4; a++)
#pragma unroll
            for (int c = 0; c < 4; c++) {
                float s = acc[a][c] + b2[co0 + c];
                y2s[(bb0 + a) * 448 + (co0 + c) * 7 + p] = eluf(s);
            }
    }

    const int co0 = (t & 31) * 4;
    const int bb0 = (t >> 5) * 2;
    float acc3[2][4];
#pragma unroll
    for (int a = 0; a < 2; a++)
#pragma unroll
        for (int c = 0; c < 4; c++) acc3[a][c] = 0.0f;

    for (int ch = 0; ch < 7; ch++) {
        int ic = ch * 64;
        __syncthreads();
        for (int idx = t; idx < 8192; idx += 256) {
            int co = idx >> 6, ii = idx & 63;
            w3c[ii * 129 + co] = w3[co * 448 + ic + ii];
        }
        __syncthreads();
#pragma unroll 4
        for (int ii = 0; ii < 64; ii++) {
            float wv0 = w3c[ii * 129 + co0 + 0];
            float wv1 = w3c[ii * 129 + co0 + 1];
            float wv2 = w3c[ii * 129 + co0 + 2];
            float wv3 = w3c[ii * 129 + co0 + 3];
#pragma unroll
            for (int a = 0; a < 2; a++) {
                float yv = y2s[(bb0 + a) * 448 + ic + ii];
                acc3[a][0] += yv * wv0;
                acc3[a][1] += yv * wv1;
                acc3[a][2] += yv * wv2;
                acc3[a][3] += yv * wv3;
            }
        }
    }
#pragma unroll
    for (int a = 0; a < 2; a++)
#pragma unroll
        for (int c = 0; c < 4; c++) {
            float s = acc3[a][c] + b3[co0 + c];
            g_feat[(size_t)(b0 + bb0 + a) * 128 + co0 + c] = eluf(s);
        }
}

// ---------------- fp16 mma.sync LSTM-cell GEMM ----------------
// SMEM words: B ring 3x8192 @0, A ring 3x1024 @24576 (half2 words, swizzled),
// gate staging [64][516] reuses 0..33023, bias @33024, hw @33536. Total 34688.
#define SMEM_GEMM_WORDS 34688
#define SMEM_GEMM_BYTES (SMEM_GEMM_WORDS * 4)
#define AOFF 24576

__global__ __launch_bounds__(512, 1)
void lstm_mma_kernel(const float* __restrict__ A0, int lda0, int k0len,
                     const float* __restrict__ A1, int lda1, int k1len,
                     const uint32_t* __restrict__ Wp,
                     const float* __restrict__ bias,
                     const float* __restrict__ Cprev,
                     float* __restrict__ Hout, float* __restrict__ Cout,
                     const float* __restrict__ headW, const float* __restrict__ headB,
                     float* __restrict__ logits)
{
    extern __shared__ float sm[];
    uint32_t* smw = (uint32_t*)sm;
    float* bias_s = sm + 33024;
    float* hw_s   = sm + 33536;
    uint32_t smb = smem_u32(sm);

    const int tid  = threadIdx.x;
    const int wid  = tid >> 5;
    const int lane = tid & 31;
    const int g    = lane >> 2;
    const int t4   = lane & 3;
    const int wm   = wid & 1;
    const int wn   = wid >> 1;
    const int row0 = blockIdx.x * 64;
    const int ar   = tid >> 3;      // A row this thread loads
    const int aq   = tid & 7;       // A quad (4 floats)

    bias_s[tid] = bias[tid];
    if (logits) {
        for (int idx = tid; idx < 1152; idx += 512) {
            int j = idx / 9, o = idx - j * 9;
            hw_s[idx] = headW[o * 128 + j];
        }
    }
    __syncthreads();

    float acc[2][8][4];
#pragma unroll
    for (int mt = 0; mt < 2; mt++)
#pragma unroll
        for (int j8 = 0; j8 < 8; j8++)
#pragma unroll
            for (int q = 0; q < 4; q++) acc[mt][j8][q] = 0.0f;

    const int nch = (k0len + k1len) >> 5;

    // ---- A load/convert/store helpers ----
    const int awsw = (2 * aq) ^ (2 * (ar & 7));   // swizzled even word-in-row
    auto ldgA = [&](int i) -> float4 {
        int kb = i << 5;
        const float* src; int ld; int col;
        if (kb < k0len) { src = A0; ld = lda0; col = kb; }
        else            { src = A1; ld = lda1; col = kb - k0len; }
        return *(const float4*)(src + (size_t)(row0 + ar) * ld + col + aq * 4);
    };
    auto stsA = [&](int i, float4 v) {
        uint32_t* p = smw + AOFF + (i % 3) * 1024 + ar * 16 + awsw;
        p[0] = pack_h2(v.x, v.y);
        p[1] = pack_h2(v.z, v.w);
    };
    auto issueB = [&](int i) {
        const uint32_t* wsrc = Wp + (size_t)i * 8192;
        uint32_t bbase = smb + (uint32_t)(i % 3) * 32768u;
#pragma unroll
        for (int it = 0; it < 4; it++) {
            int gi = it * 512 + tid;
            CP16(bbase + (uint32_t)gi * 16u, wsrc + (size_t)gi * 4);
        }
        CP_COMMIT();
    };

    // ---- prologue ----
    float4 hold;
    {
        float4 a0v = ldgA(0);
        stsA(0, a0v);
        issueB(0);
        if (nch > 1) { hold = ldgA(1); issueB(1); }
    }

    const int xg = 2 * g;
    for (int i = 0; i < nch; i++) {
        if (i == nch - 1) { CP_WAIT0(); } else { CP_WAIT1(); }
        __syncthreads();
        if (i + 1 < nch) stsA(i + 1, hold);
        if (i + 2 < nch) { hold = ldgA(i + 2); issueB(i + 2); }

        const uint32_t* Aw = smw + AOFF + (i % 3) * 1024;
        const uint4*    Bq = (const uint4*)(smw + (i % 3) * 8192 + wn * 1024);

#pragma unroll
        for (int s = 0; s < 2; s++) {
            uint4 bv[4];
#pragma unroll
            for (int jp = 0; jp < 4; jp++) bv[jp] = Bq[s * 128 + jp * 32 + lane];
            uint32_t a[2][4];
#pragma unroll
            for (int mt = 0; mt < 2; mt++) {
                int r0 = wm * 32 + mt * 16 + g;
                int w0 = (s * 8 + t4) ^ xg;
                int w1 = (s * 8 + 4 + t4) ^ xg;
                a[mt][0] = Aw[r0 * 16 + w0];
                a[mt][1] = Aw[(r0 + 8) * 16 + w0];
                a[mt][2] = Aw[r0 * 16 + w1];
                a[mt][3] = Aw[(r0 + 8) * 16 + w1];
            }
#pragma unroll
            for (int jp = 0; jp < 4; jp++) {
                MMA_F16(acc[0][2 * jp],     a[0], bv[jp].x, bv[jp].y);
                MMA_F16(acc[1][2 * jp],     a[1], bv[jp].x, bv[jp].y);
                MMA_F16(acc[0][2 * jp + 1], a[0], bv[jp].z, bv[jp].w);
                MMA_F16(acc[1][2 * jp + 1], a[1], bv[jp].z, bv[jp].w);
            }
        }
    }
    __syncthreads();

    // ---- stage gates to smem [64][516] (reuses B/A region) ----
#pragma unroll
    for (int mt = 0; mt < 2; mt++) {
        int row = wm * 32 + mt * 16 + g;
#pragma unroll
        for (int j8 = 0; j8 < 8; j8++) {
            int col = wn * 64 + j8 * 8 + 2 * t4;
            sm[row * 516 + col]           = acc[mt][j8][0];
            sm[row * 516 + col + 1]       = acc[mt][j8][1];
            sm[(row + 8) * 516 + col]     = acc[mt][j8][2];
            sm[(row + 8) * 516 + col + 1] = acc[mt][j8][3];
        }
    }
    __syncthreads();

    // ---- LSTM cell epilogue ----
    const int j  = tid & 127;
    const int rg = tid >> 7;
    const float bi = bias_s[j], bf = bias_s[128 + j], bg = bias_s[256 + j], bo = bias_s[384 + j];
#pragma unroll
    for (int rr = 0; rr < 16; rr++) {
        int r = rg * 16 + rr;
        int row = row0 + r;
        float gi = sm[r * 516 + j]       + bi;
        float gf = sm[r * 516 + 128 + j] + bf;
        float gg = sm[r * 516 + 256 + j] + bg;
        float go = sm[r * 516 + 384 + j] + bo;
        float cp = Cprev ? Cprev[(size_t)row * 128 + j] : 0.0f;
        float c  = sigf(gf) * cp + sigf(gi) * tanhx(gg);
        float h  = sigf(go) * tanhx(c);
        Cout[(size_t)row * 128 + j] = c;
        Hout[(size_t)row * 128 + j] = h;
        sm[r * 516 + j] = h;
    }

    if (logits) {
        __syncthreads();
        for (int idx = tid; idx < 576; idx += 512) {
            int r = idx / 9, o = idx - r * 9;
            const float* hr = sm + r * 516;
            float ssum = headB[o];
#pragma unroll 8
            for (int jj = 0; jj < 128; jj++) ssum += hr[jj] * hw_s[jj * 9 + o];
            logits[(size_t)(row0 + r) * 9 + o] = ssum;
        }
    }
}

// ---------------- launch ----------------
extern "C" void kernel_launch(void* const* d_in, const int* in_sizes, int n_in,
                              void* d_out, int out_size) {
    const float* x        = (const float*)d_in[0];
    const float* ps       = (const float*)d_in[1];
    const float* conv1_w  = (const float*)d_in[2];
    const float* conv1_b  = (const float*)d_in[3];
    const float* conv2_w  = (const float*)d_in[4];
    const float* conv2_b  = (const float*)d_in[5];
    const float* conv3_w  = (const float*)d_in[6];
    const float* conv3_b  = (const float*)d_in[7];
    const float* w_ih1    = (const float*)d_in[8];
    const float* w_hh1    = (const float*)d_in[9];
    const float* b_ih1    = (const float*)d_in[10];
    const float* b_hh1    = (const float*)d_in[11];
    const float* w_ih2    = (const float*)d_in[12];
    const float* w_hh2    = (const float*)d_in[13];
    const float* b_ih2    = (const float*)d_in[14];
    const float* b_hh2    = (const float*)d_in[15];
    const float* head_w   = (const float*)d_in[16];
    const float* head_b   = (const float*)d_in[17];
    float* out = (float*)d_out;

    const int conv_smem = 37008 * 4;
    cudaFuncSetAttribute(conv_kernel, cudaFuncAttributeMaxDynamicSharedMemorySize, conv_smem);
    cudaFuncSetAttribute(lstm_mma_kernel, cudaFuncAttributeMaxDynamicSharedMemorySize, SMEM_GEMM_BYTES);

    float *feat, *h1, *c1, *h2, *c2, *b1, *b2;
    uint32_t *W1h, *W2h;
    cudaGetSymbolAddress((void**)&feat, g_feat);
    cudaGetSymbolAddress((void**)&h1, g_h1);
    cudaGetSymbolAddress((void**)&c1, g_c1);
    cudaGetSymbolAddress((void**)&h2, g_h2);
    cudaGetSymbolAddress((void**)&c2, g_c2);
    cudaGetSymbolAddress((void**)&W1h, g_W1h);
    cudaGetSymbolAddress((void**)&W2h, g_W2h);
    cudaGetSymbolAddress((void**)&b1, g_b1);
    cudaGetSymbolAddress((void**)&b2, g_b2);

    const int prep_total = 12 * 8192 + 8 * 8192 + 1024;
    prep_kernel<<<(prep_total + 255) / 256, 256>>>(w_ih1, w_hh1, b_ih1, b_hh1,
                                                   w_ih2, w_hh2, b_ih2, b_hh2);

    conv_kernel<<<Bn / 16, 256, conv_smem>>>(x, conv1_w, conv1_b, conv2_w, conv2_b,
                                             conv3_w, conv3_b);

    const int grid = Bn / 64;
    // step 0: input = [feat, 0], h=c=0; k>=128 contributes nothing for L1
    lstm_mma_kernel<<<grid, 512, SMEM_GEMM_BYTES>>>(
        feat, 128, 128, nullptr, 0, 0, W1h, b1,
        nullptr, h1, c1, head_w, head_b, nullptr);
    lstm_mma_kernel<<<grid, 512, SMEM_GEMM_BYTES>>>(
        h1, 128, 128, nullptr, 0, 0, W2h, b2,
        nullptr, h2, c2, head_w, head_b, out);
    // steps 1..16
    for (int s = 1; s <= Tn; s++) {
        const float* A = ps + (size_t)(s - 1) * Bn * 256;
        lstm_mma_kernel<<<grid, 512, SMEM_GEMM_BYTES>>>(
            A, 256, 256, h1, 128, 128, W1h, b1,
            c1, h1, c1, head_w, head_b, nullptr);
        lstm_mma_kernel<<<grid, 512, SMEM_GEMM_BYTES>>>(
            h1, 128, 128, h2, 128, 128, W2h, b2,
            c2, h2, c2, head_w, head_b, out + (size_t)s * Bn * 9);
    }
}

// round 9
// speedup vs baseline: 1.8124x; 1.2845x over previous
#include <cuda_runtime.h>
#include <cuda_fp16.h>
#include <math.h>
#include <stdint.h>

#define Bn 32768
#define Tn 16

// ---------------- device scratch ----------------
__device__ float    g_feat[Bn * 128];
__device__ float    g_h1[Bn * 128];
__device__ float    g_c1[Bn * 128];
__device__ float    g_h2[Bn * 128];
__device__ float    g_c2[Bn * 128];
__device__ uint32_t g_W1h[12 * 8192];   // [ch][half][wn2][s][jp][lane][w] half2 words
__device__ uint32_t g_W2h[8 * 8192];
__device__ float    g_b1p[512];         // gate-interleaved n' = 4j+gate
__device__ float    g_b2p[512];

// ---------------- helpers ----------------
__device__ __forceinline__ uint32_t smem_u32(const void* p) {
    uint32_t r;
    asm("{ .reg .u64 t; cvta.to.shared.u64 t, %1; cvt.u32.u64 %0, t; }" : "=r"(r) : "l"(p));
    return r;
}
#define CP16(dst, src) asm volatile("cp.async.cg.shared.global [%0], [%1], 16;" :: "r"(dst), "l"(src))
#define CP_COMMIT()    asm volatile("cp.async.commit_group;" ::: "memory")
#define CP_WAIT0()     asm volatile("cp.async.wait_group 0;" ::: "memory")
#define CP_WAIT1()     asm volatile("cp.async.wait_group 1;" ::: "memory")

#define MMA_F16(d, a, b0v, b1v) \
    asm volatile("mma.sync.aligned.m16n8k16.row.col.f32.f16.f16.f32 " \
        "{%0,%1,%2,%3}, {%4,%5,%6,%7}, {%8,%9}, {%0,%1,%2,%3};" \
        : "+f"((d)[0]), "+f"((d)[1]), "+f"((d)[2]), "+f"((d)[3]) \
        : "r"((a)[0]), "r"((a)[1]), "r"((a)[2]), "r"((a)[3]), "r"(b0v), "r"(b1v))

__device__ __forceinline__ uint32_t pack_h2(float lo, float hi) {
    __half2 h = __floats2half2_rn(lo, hi);
    uint32_t u;
    memcpy(&u, &h, 4);
    return u;
}
__device__ __forceinline__ float sigf(float x) { return __fdividef(1.0f, 1.0f + __expf(-x)); }
__device__ __forceinline__ float tanhx(float x) { return __fdividef(2.0f, 1.0f + __expf(-2.0f * x)) - 1.0f; }
__device__ __forceinline__ float eluf(float x) { return x > 0.0f ? x : expm1f(x); }

// ---------------- weight prep ----------------
// li bits: w(2) lane(5) jp(2) s(1) wn2(2) half(1) ch(rest)
// j8 = 2*jp + (w>>1); k = ch*32 + s*16 + 8*(w&1) + 2*t4;
// n' = half*256 + wn2*64 + j8*8 + g;  j = n'>>2, gate = n'&3, n = gate*128 + j
__global__ void prep_kernel(const float* __restrict__ w_ih1, const float* __restrict__ w_hh1,
                            const float* __restrict__ b_ih1, const float* __restrict__ b_hh1,
                            const float* __restrict__ w_ih2, const float* __restrict__ w_hh2,
                            const float* __restrict__ b_ih2, const float* __restrict__ b_hh2) {
    int i = blockIdx.x * blockDim.x + threadIdx.x;
    const int total1 = 12 * 8192;
    const int total2 = 8 * 8192;
    if (i < total1 + total2) {
        int li = (i < total1) ? i : i - total1;
        int w    = li & 3;
        int lane = (li >> 2) & 31;
        int jp   = (li >> 7) & 3;
        int s    = (li >> 9) & 1;
        int wn2  = (li >> 10) & 3;
        int half = (li >> 12) & 1;
        int ch   = li >> 13;
        int g = lane >> 2, t4 = lane & 3;
        int j8 = jp * 2 + (w >> 1);
        int k  = ch * 32 + s * 16 + 8 * (w & 1) + 2 * t4;
        int np = half * 256 + wn2 * 64 + j8 * 8 + g;
        int j = np >> 2, gate = np & 3;
        int n = gate * 128 + j;
        float f0, f1;
        if (i < total1) {
            if (k < 256) { f0 = w_ih1[n * 256 + k];        f1 = w_ih1[n * 256 + k + 1]; }
            else         { f0 = w_hh1[n * 128 + k - 256];  f1 = w_hh1[n * 128 + k - 255]; }
            g_W1h[li] = pack_h2(f0, f1);
        } else {
            if (k < 128) { f0 = w_ih2[n * 128 + k];        f1 = w_ih2[n * 128 + k + 1]; }
            else         { f0 = w_hh2[n * 128 + k - 128];  f1 = w_hh2[n * 128 + k - 127]; }
            g_W2h[li] = pack_h2(f0, f1);
        }
    } else if (i < total1 + total2 + 512) {
        int np = i - total1 - total2;
        int j = np >> 2, gate = np & 3;
        int n = gate * 128 + j;
        g_b1p[np] = b_ih1[n] + b_hh1[n];
    } else if (i < total1 + total2 + 1024) {
        int np = i - total1 - total2 - 512;
        int j = np >> 2, gate = np & 3;
        int n = gate * 128 + j;
        g_b2p[np] = b_ih2[n] + b_hh2[n];
    }
}

// ---------------- fused conv stack (w2 chunked: 105KB smem -> 2 CTA/SM) ----------------
__launch_bounds__(256, 2)
__global__ void conv_kernel(const float* __restrict__ x,
                            const float* __restrict__ w1, const float* __restrict__ b1,
                            const float* __restrict__ w2, const float* __restrict__ b2,
                            const float* __restrict__ w3, const float* __restrict__ b3) {
    extern __shared__ float sm[];
    float* xs  = sm;                 // 304
    float* y1s = xs + 304;           // 6656
    float* y2s = y1s + 6656;         // 7168
    float* w1s = y2s + 7168;         // 224
    float* w2s = w1s + 224;          // 64*57 = 3648
    float* w3c = w2s + 3648;         // 8256   total 26256 words = 105KB

    const int t  = threadIdx.x;
    const int b0 = blockIdx.x * 16;

    for (int idx = t; idx < 16 * 19; idx += 256) xs[idx] = x[b0 * 19 + idx];
    for (int idx = t; idx < 224; idx += 256)     w1s[idx] = w1[idx];
    __syncthreads();

    for (int idx = t; idx < 16 * 416; idx += 256) {
        int b = idx / 416, rem = idx - b * 416;
        int co = rem / 13, p = rem - co * 13;
        float s = b1[co];
#pragma unroll
        for (int k = 0; k < 7; k++) s += xs[b * 19 + p + k] * w1s[co * 7 + k];
        y1s[idx] = eluf(s);
    }

    // conv2 with w2 chunked over ci (4 groups of 8), accumulators persist
    float acc2[2][4][4];
#pragma unroll
    for (int uu = 0; uu < 2; uu++)
#pragma unroll
        for (int a = 0; a < 4; a++)
#pragma unroll
            for (int c = 0; c < 4; c++) acc2[uu][a][c] = 0.0f;

    for (int cig = 0; cig < 4; cig++) {
        __syncthreads();
        for (int idx = t; idx < 3584; idx += 256) {
            int co = idx / 56, rem = idx - co * 56;
            w2s[co * 57 + rem] = w2[co * 224 + cig * 56 + rem];
        }
        __syncthreads();
#pragma unroll
        for (int uu = 0; uu < 2; uu++) {
            int u = t + uu * 256;
            if (u >= 448) break;
            int p = u % 7;
            int cog = (u / 7) & 15;
            int bg = u / 112;
            int bb0 = bg * 4, co0 = cog * 4;
            for (int cil = 0; cil < 8; cil++) {
                int ci = cig * 8 + cil;
                float yv[4][7];
#pragma unroll
                for (int a = 0; a < 4; a++)
#pragma unroll
                    for (int k = 0; k < 7; k++)
                        yv[a][k] = y1s[(bb0 + a) * 416 + ci * 13 + p + k];
#pragma unroll
                for (int c = 0; c < 4; c++)
#pragma unroll
                    for (int k = 0; k < 7; k++) {
                        float wv = w2s[(co0 + c) * 57 + cil * 7 + k];
#pragma unroll
                        for (int a = 0; a < 4; a++) acc2[uu][a][c] += yv[a][k] * wv;
                    }
            }
        }
    }
    __syncthreads();
#pragma unroll
    for (int uu = 0; uu < 2; uu++) {
        int u = t + uu * 256;
        if (u >= 448) break;
        int p = u % 7;
        int cog = (u / 7) & 15;
        int bg = u / 112;
        int bb0 = bg * 4, co0 = cog * 4;
#pragma unroll
        for (int a = 0; a < 4; a++)
#pragma unroll
            for (int c = 0; c < 4; c++) {
                float s = acc2[uu][a][c] + b2[co0 + c];
                y2s[(bb0 + a) * 448 + (co0 + c) * 7 + p] = eluf(s);
            }
    }

    const int co0 = (t & 31) * 4;
    const int bb0 = (t >> 5) * 2;
    float acc3[2][4];
#pragma unroll
    for (int a = 0; a < 2; a++)
#pragma unroll
        for (int c = 0; c < 4; c++) acc3[a][c] = 0.0f;

    for (int ch = 0; ch < 7; ch++) {
        int ic = ch * 64;
        __syncthreads();
        for (int idx = t; idx < 8192; idx += 256) {
            int co = idx >> 6, ii = idx & 63;
            w3c[ii * 129 + co] = w3[co * 448 + ic + ii];
        }
        __syncthreads();
#pragma unroll 4
        for (int ii = 0; ii < 64; ii++) {
            float wv0 = w3c[ii * 129 + co0 + 0];
            float wv1 = w3c[ii * 129 + co0 + 1];
            float wv2 = w3c[ii * 129 + co0 + 2];
            float wv3 = w3c[ii * 129 + co0 + 3];
#pragma unroll
            for (int a = 0; a < 2; a++) {
                float yv = y2s[(bb0 + a) * 448 + ic + ii];
                acc3[a][0] += yv * wv0;
                acc3[a][1] += yv * wv1;
                acc3[a][2] += yv * wv2;
                acc3[a][3] += yv * wv3;
            }
        }
    }
#pragma unroll
    for (int a = 0; a < 2; a++)
#pragma unroll
        for (int c = 0; c < 4; c++) {
            float s = acc3[a][c] + b3[co0 + c];
            g_feat[(size_t)(b0 + bb0 + a) * 128 + co0 + c] = eluf(s);
        }
}

// ---------------- fp16 LSTM-cell GEMM, half-N CTA (256 thr, 2 CTA/SM) ----------------
// smem words: B ring 3x4096 @0, A ring 3x1024 @12288, staging [64][260] @0 (reuse),
// bias @16640 (256), hw @16896 (1152). Total 18048 words = 72192 B.
#define SMEM_LSTM_WORDS 18048
#define SMEM_LSTM_BYTES (SMEM_LSTM_WORDS * 4)
#define AOFF 12288
#define BIASO 16640
#define HWO  16896

__global__ __launch_bounds__(256, 2)
void lstm_mma_kernel(const float* __restrict__ A0, int lda0, int k0len,
                     const float* __restrict__ A1, int k1len,
                     const uint32_t* __restrict__ Wp,
                     const float* __restrict__ biasp,
                     const float* __restrict__ Cprev,
                     float* __restrict__ Hout, float* __restrict__ Cout,
                     const float* __restrict__ h2head,   // if non-null: compute head
                     const float* __restrict__ headW, const float* __restrict__ headB,
                     float* __restrict__ outPrev)
{
    extern __shared__ float sm[];
    uint32_t* smw = (uint32_t*)sm;
    float* bias_s = sm + BIASO;
    float* hw_s   = sm + HWO;
    uint32_t smb = smem_u32(sm);

    const int tid  = threadIdx.x;
    const int wid  = tid >> 5;
    const int lane = tid & 31;
    const int g    = lane >> 2;
    const int t4   = lane & 3;
    const int wm   = wid & 1;
    const int wn2  = wid >> 1;
    const int half = blockIdx.x & 1;
    const int row0 = (blockIdx.x >> 1) * 64;
    const int ar   = tid >> 3;      // A row (0..31), second unit +32
    const int aq   = tid & 7;

    bias_s[tid] = biasp[half * 256 + tid];
    if (h2head) {
        for (int idx = tid; idx < 1152; idx += 256) {
            int j = idx / 9, o = idx - j * 9;
            hw_s[idx] = headW[o * 128 + j];
        }
    }
    __syncthreads();

    float acc[2][8][4];
#pragma unroll
    for (int mt = 0; mt < 2; mt++)
#pragma unroll
        for (int j8 = 0; j8 < 8; j8++)
#pragma unroll
            for (int q = 0; q < 4; q++) acc[mt][j8][q] = 0.0f;

    const int nch = (k0len + k1len) >> 5;
    const int awsw = (2 * aq) ^ (2 * (ar & 7));

    auto ldgA = [&](int i, float4 v[2]) {
        int kb = i << 5;
        const float* src; int ld; int col;
        if (kb < k0len) { src = A0; ld = lda0; col = kb; }
        else            { src = A1; ld = 128;  col = kb - k0len; }
        v[0] = *(const float4*)(src + (size_t)(row0 + ar) * ld + col + aq * 4);
        v[1] = *(const float4*)(src + (size_t)(row0 + ar + 32) * ld + col + aq * 4);
    };
    auto stsA = [&](int i, const float4 v[2]) {
        uint32_t* p = smw + AOFF + (i % 3) * 1024 + ar * 16 + awsw;
        p[0] = pack_h2(v[0].x, v[0].y);
        p[1] = pack_h2(v[0].z, v[0].w);
        p[512] = pack_h2(v[1].x, v[1].y);
        p[513] = pack_h2(v[1].z, v[1].w);
    };
    auto issueB = [&](int i) {
        const uint32_t* wsrc = Wp + (size_t)(i * 2 + half) * 4096;
        uint32_t bbase = smb + (uint32_t)(i % 3) * 16384u;
#pragma unroll
        for (int it = 0; it < 4; it++) {
            int gi = it * 256 + tid;
            CP16(bbase + (uint32_t)gi * 16u, wsrc + (size_t)gi * 4);
        }
        CP_COMMIT();
    };

    // prologue
    float4 hold[2];
    {
        float4 a0v[2];
        ldgA(0, a0v);
        stsA(0, a0v);
        issueB(0);
        if (nch > 1) { ldgA(1, hold); issueB(1); }
    }

    const int xg = 2 * g;
    for (int i = 0; i < nch; i++) {
        if (i == nch - 1) { CP_WAIT0(); } else { CP_WAIT1(); }
        __syncthreads();
        if (i + 1 < nch) stsA(i + 1, hold);
        if (i + 2 < nch) { ldgA(i + 2, hold); issueB(i + 2); }

        const uint32_t* Aw = smw + AOFF + (i % 3) * 1024;
        const uint4*    Bq = (const uint4*)(smw + (i % 3) * 4096) + wn2 * 256;

#pragma unroll
        for (int s = 0; s < 2; s++) {
            uint4 bv[4];
#pragma unroll
            for (int jp = 0; jp < 4; jp++) bv[jp] = Bq[s * 128 + jp * 32 + lane];
            uint32_t a[2][4];
#pragma unroll
            for (int mt = 0; mt < 2; mt++) {
                int r0 = wm * 32 + mt * 16 + g;
                int w0 = (s * 8 + t4) ^ xg;
                int w1 = (s * 8 + 4 + t4) ^ xg;
                a[mt][0] = Aw[r0 * 16 + w0];
                a[mt][1] = Aw[(r0 + 8) * 16 + w0];
                a[mt][2] = Aw[r0 * 16 + w1];
                a[mt][3] = Aw[(r0 + 8) * 16 + w1];
            }
#pragma unroll
            for (int jp = 0; jp < 4; jp++) {
                MMA_F16(acc[0][2 * jp],     a[0], bv[jp].x, bv[jp].y);
                MMA_F16(acc[1][2 * jp],     a[1], bv[jp].x, bv[jp].y);
                MMA_F16(acc[0][2 * jp + 1], a[0], bv[jp].z, bv[jp].w);
                MMA_F16(acc[1][2 * jp + 1], a[1], bv[jp].z, bv[jp].w);
            }
        }
    }
    __syncthreads();

    // stage gates to [64][260]
#pragma unroll
    for (int mt = 0; mt < 2; mt++) {
        int row = wm * 32 + mt * 16 + g;
#pragma unroll
        for (int j8 = 0; j8 < 8; j8++) {
            int col = wn2 * 64 + j8 * 8 + 2 * t4;
            sm[row * 260 + col]           = acc[mt][j8][0];
            sm[row * 260 + col + 1]       = acc[mt][j8][1];
            sm[(row + 8) * 260 + col]     = acc[mt][j8][2];
            sm[(row + 8) * 260 + col + 1] = acc[mt][j8][3];
        }
    }
    __syncthreads();

    // cell epilogue: thread j0 = tid&63, 4 row-groups of 16
    {
        const int j0 = tid & 63;
        const int rg = tid >> 6;
        const int col = half * 64 + j0;
        const float4 bb = *(const float4*)(bias_s + 4 * j0);
#pragma unroll
        for (int rr = 0; rr < 16; rr++) {
            int r = rg * 16 + rr;
            int row = row0 + r;
            float4 gv = *(const float4*)(sm + r * 260 + 4 * j0);
            float gi = gv.x + bb.x;
            float gf = gv.y + bb.y;
            float gg = gv.z + bb.z;
            float go = gv.w + bb.w;
            float cp = Cprev ? Cprev[(size_t)row * 128 + col] : 0.0f;
            float c  = sigf(gf) * cp + sigf(gi) * tanhx(gg);
            float h  = sigf(go) * tanhx(c);
            Cout[(size_t)row * 128 + col] = c;
            Hout[(size_t)row * 128 + col] = h;
        }
    }

    // head for previous step's h2 (32 rows per CTA)
    if (h2head) {
        __syncthreads();
        const int hr0 = row0 + half * 32;
#pragma unroll
        for (int it = 0; it < 4; it++) {
            int idx = tid + it * 256;
            int r = idx >> 5, cq = idx & 31;
            float4 v = *(const float4*)(h2head + (size_t)(hr0 + r) * 128 + cq * 4);
            sm[r * 132 + cq * 4]     = v.x;
            sm[r * 132 + cq * 4 + 1] = v.y;
            sm[r * 132 + cq * 4 + 2] = v.z;
            sm[r * 132 + cq * 4 + 3] = v.w;
        }
        __syncthreads();
        for (int idx = tid; idx < 288; idx += 256) {
            int r = idx / 9, o = idx - r * 9;
            float s = headB[o];
            const float* hr = sm + r * 132;
#pragma unroll 8
            for (int jj = 0; jj < 128; jj++) s += hr[jj] * hw_s[jj * 9 + o];
            outPrev[(size_t)(hr0 + r) * 9 + o] = s;
        }
    }
}

// ---------------- final head kernel (step 16) ----------------
__global__ __launch_bounds__(256)
void head_kernel(const float* __restrict__ h2,
                 const float* __restrict__ headW, const float* __restrict__ headB,
                 float* __restrict__ outp)
{
    __shared__ float hs[64 * 132];
    __shared__ float hw[1152];
    const int t = threadIdx.x;
    const int r0 = blockIdx.x * 64;
    for (int idx = t; idx < 1152; idx += 256) {
        int j = idx / 9, o = idx - j * 9;
        hw[idx] = headW[o * 128 + j];
    }
#pragma unroll
    for (int it = 0; it < 8; it++) {
        int idx = t + it * 256;
        int r = idx >> 5, cq = idx & 31;
        float4 v = *(const float4*)(h2 + (size_t)(r0 + r) * 128 + cq * 4);
        hs[r * 132 + cq * 4]     = v.x;
        hs[r * 132 + cq * 4 + 1] = v.y;
        hs[r * 132 + cq * 4 + 2] = v.z;
        hs[r * 132 + cq * 4 + 3] = v.w;
    }
    __syncthreads();
    for (int idx = t; idx < 576; idx += 256) {
        int r = idx / 9, o = idx - r * 9;
        float s = headB[o];
        const float* hr = hs + r * 132;
#pragma unroll 8
        for (int jj = 0; jj < 128; jj++) s += hr[jj] * hw[jj * 9 + o];
        outp[(size_t)(r0 + r) * 9 + o] = s;
    }
}

// ---------------- launch ----------------
extern "C" void kernel_launch(void* const* d_in, const int* in_sizes, int n_in,
                              void* d_out, int out_size) {
    const float* x        = (const float*)d_in[0];
    const float* ps       = (const float*)d_in[1];
    const float* conv1_w  = (const float*)d_in[2];
    const float* conv1_b  = (const float*)d_in[3];
    const float* conv2_w  = (const float*)d_in[4];
    const float* conv2_b  = (const float*)d_in[5];
    const float* conv3_w  = (const float*)d_in[6];
    const float* conv3_b  = (const float*)d_in[7];
    const float* w_ih1    = (const float*)d_in[8];
    const float* w_hh1    = (const float*)d_in[9];
    const float* b_ih1    = (const float*)d_in[10];
    const float* b_hh1    = (const float*)d_in[11];
    const float* w_ih2    = (const float*)d_in[12];
    const float* w_hh2    = (const float*)d_in[13];
    const float* b_ih2    = (const float*)d_in[14];
    const float* b_hh2    = (const float*)d_in[15];
    const float* head_w   = (const float*)d_in[16];
    const float* head_b   = (const float*)d_in[17];
    float* out = (float*)d_out;

    const int conv_smem = 26256 * 4;
    cudaFuncSetAttribute(conv_kernel, cudaFuncAttributeMaxDynamicSharedMemorySize, conv_smem);
    cudaFuncSetAttribute(lstm_mma_kernel, cudaFuncAttributeMaxDynamicSharedMemorySize, SMEM_LSTM_BYTES);

    float *feat, *h1, *c1, *h2, *c2, *b1p, *b2p;
    uint32_t *W1h, *W2h;
    cudaGetSymbolAddress((void**)&feat, g_feat);
    cudaGetSymbolAddress((void**)&h1, g_h1);
    cudaGetSymbolAddress((void**)&c1, g_c1);
    cudaGetSymbolAddress((void**)&h2, g_h2);
    cudaGetSymbolAddress((void**)&c2, g_c2);
    cudaGetSymbolAddress((void**)&W1h, g_W1h);
    cudaGetSymbolAddress((void**)&W2h, g_W2h);
    cudaGetSymbolAddress((void**)&b1p, g_b1p);
    cudaGetSymbolAddress((void**)&b2p, g_b2p);

    const int prep_total = 12 * 8192 + 8 * 8192 + 1024;
    prep_kernel<<<(prep_total + 255) / 256, 256>>>(w_ih1, w_hh1, b_ih1, b_hh1,
                                                   w_ih2, w_hh2, b_ih2, b_hh2);

    conv_kernel<<<Bn / 16, 256, conv_smem>>>(x, conv1_w, conv1_b, conv2_w, conv2_b,
                                             conv3_w, conv3_b);

    const int grid = (Bn / 64) * 2;   // 1024 CTAs: (rowtile, half)
    // step 0
    lstm_mma_kernel<<<grid, 256, SMEM_LSTM_BYTES>>>(
        feat, 128, 128, nullptr, 0, W1h, b1p,
        nullptr, h1, c1, nullptr, nullptr, nullptr, nullptr);
    lstm_mma_kernel<<<grid, 256, SMEM_LSTM_BYTES>>>(
        h1, 128, 128, nullptr, 0, W2h, b2p,
        nullptr, h2, c2, nullptr, nullptr, nullptr, nullptr);
    // steps 1..16; L1 of step s also emits logits for step s-1 from current h2
    for (int s = 1; s <= Tn; s++) {
        const float* A = ps + (size_t)(s - 1) * Bn * 256;
        lstm_mma_kernel<<<grid, 256, SMEM_LSTM_BYTES>>>(
            A, 256, 256, h1, 128, W1h, b1p,
            c1, h1, c1, h2, head_w, head_b, out + (size_t)(s - 1) * Bn * 9);
        lstm_mma_kernel<<<grid, 256, SMEM_LSTM_BYTES>>>(
            h1, 128, 128, h2, 128, W2h, b2p,
            c2, h2, c2, nullptr, nullptr, nullptr, nullptr);
    }
    // final head for step 16
    head_kernel<<<Bn / 64, 256>>>(h2, head_w, head_b, out + (size_t)Tn * Bn * 9);
}

// round 10
// speedup vs baseline: 1.8889x; 1.0422x over previous
#include <cuda_runtime.h>
#include <cuda_fp16.h>
#include <math.h>
#include <stdint.h>

#define Bn 32768
#define Tn 16
#define BH (Bn * 128)

// ---------------- device scratch ----------------
__device__ float    g_feat[Bn * 128];
__device__ float    g_h1[2 * BH];
__device__ float    g_c1[BH];
__device__ float    g_h2[2 * BH];
__device__ float    g_c2[BH];
__device__ uint32_t g_W1h[12 * 8192];   // [ch][half][wn2][s][jp][lane][w] half2 words
__device__ uint32_t g_W2h[8 * 8192];
__device__ float    g_b1p[512];         // gate-interleaved n' = 4j+gate
__device__ float    g_b2p[512];

// ---------------- helpers ----------------
__device__ __forceinline__ uint32_t smem_u32(const void* p) {
    uint32_t r;
    asm("{ .reg .u64 t; cvta.to.shared.u64 t, %1; cvt.u32.u64 %0, t; }" : "=r"(r) : "l"(p));
    return r;
}
#define CP16(dst, src) asm volatile("cp.async.cg.shared.global [%0], [%1], 16;" :: "r"(dst), "l"(src))
#define CP_COMMIT()    asm volatile("cp.async.commit_group;" ::: "memory")
#define CP_WAIT0()     asm volatile("cp.async.wait_group 0;" ::: "memory")
#define CP_WAIT1()     asm volatile("cp.async.wait_group 1;" ::: "memory")

#define MMA_F16(d, a, b0v, b1v) \
    asm volatile("mma.sync.aligned.m16n8k16.row.col.f32.f16.f16.f32 " \
        "{%0,%1,%2,%3}, {%4,%5,%6,%7}, {%8,%9}, {%0,%1,%2,%3};" \
        : "+f"((d)[0]), "+f"((d)[1]), "+f"((d)[2]), "+f"((d)[3]) \
        : "r"((a)[0]), "r"((a)[1]), "r"((a)[2]), "r"((a)[3]), "r"(b0v), "r"(b1v))

__device__ __forceinline__ uint32_t pack_h2(float lo, float hi) {
    __half2 h = __floats2half2_rn(lo, hi);
    uint32_t u;
    memcpy(&u, &h, 4);
    return u;
}
__device__ __forceinline__ float sigf(float x) { return __fdividef(1.0f, 1.0f + __expf(-x)); }
__device__ __forceinline__ float tanhx(float x) { return __fdividef(2.0f, 1.0f + __expf(-2.0f * x)) - 1.0f; }
__device__ __forceinline__ float eluf(float x) { return x > 0.0f ? x : expm1f(x); }

// ---------------- weight prep ----------------
__global__ void prep_kernel(const float* __restrict__ w_ih1, const float* __restrict__ w_hh1,
                            const float* __restrict__ b_ih1, const float* __restrict__ b_hh1,
                            const float* __restrict__ w_ih2, const float* __restrict__ w_hh2,
                            const float* __restrict__ b_ih2, const float* __restrict__ b_hh2) {
    int i = blockIdx.x * blockDim.x + threadIdx.x;
    const int total1 = 12 * 8192;
    const int total2 = 8 * 8192;
    if (i < total1 + total2) {
        int li = (i < total1) ? i : i - total1;
        int w    = li & 3;
        int lane = (li >> 2) & 31;
        int jp   = (li >> 7) & 3;
        int s    = (li >> 9) & 1;
        int wn2  = (li >> 10) & 3;
        int half = (li >> 12) & 1;
        int ch   = li >> 13;
        int g = lane >> 2, t4 = lane & 3;
        int j8 = jp * 2 + (w >> 1);
        int k  = ch * 32 + s * 16 + 8 * (w & 1) + 2 * t4;
        int np = half * 256 + wn2 * 64 + j8 * 8 + g;
        int j = np >> 2, gate = np & 3;
        int n = gate * 128 + j;
        float f0, f1;
        if (i < total1) {
            if (k < 256) { f0 = w_ih1[n * 256 + k];        f1 = w_ih1[n * 256 + k + 1]; }
            else         { f0 = w_hh1[n * 128 + k - 256];  f1 = w_hh1[n * 128 + k - 255]; }
            g_W1h[li] = pack_h2(f0, f1);
        } else {
            if (k < 128) { f0 = w_ih2[n * 128 + k];        f1 = w_ih2[n * 128 + k + 1]; }
            else         { f0 = w_hh2[n * 128 + k - 128];  f1 = w_hh2[n * 128 + k - 127]; }
            g_W2h[li] = pack_h2(f0, f1);
        }
    } else if (i < total1 + total2 + 512) {
        int np = i - total1 - total2;
        int j = np >> 2, gate = np & 3;
        int n = gate * 128 + j;
        g_b1p[np] = b_ih1[n] + b_hh1[n];
    } else if (i < total1 + total2 + 1024) {
        int np = i - total1 - total2 - 512;
        int j = np >> 2, gate = np & 3;
        int n = gate * 128 + j;
        g_b2p[np] = b_ih2[n] + b_hh2[n];
    }
}

// ---------------- fused conv stack (105KB smem -> 2 CTA/SM) ----------------
__launch_bounds__(256, 2)
__global__ void conv_kernel(const float* __restrict__ x,
                            const float* __restrict__ w1, const float* __restrict__ b1,
                            const float* __restrict__ w2, const float* __restrict__ b2,
                            const float* __restrict__ w3, const float* __restrict__ b3) {
    extern __shared__ float sm[];
    float* xs  = sm;                 // 304
    float* y1s = xs + 304;           // 6656
    float* y2s = y1s + 6656;         // 7168
    float* w1s = y2s + 7168;         // 224
    float* w2s = w1s + 224;          // 3648
    float* w3c = w2s + 3648;         // 8256

    const int t  = threadIdx.x;
    const int b0 = blockIdx.x * 16;

    for (int idx = t; idx < 16 * 19; idx += 256) xs[idx] = x[b0 * 19 + idx];
    for (int idx = t; idx < 224; idx += 256)     w1s[idx] = w1[idx];
    __syncthreads();

    for (int idx = t; idx < 16 * 416; idx += 256) {
        int b = idx / 416, rem = idx - b * 416;
        int co = rem / 13, p = rem - co * 13;
        float s = b1[co];
#pragma unroll
        for (int k = 0; k < 7; k++) s += xs[b * 19 + p + k] * w1s[co * 7 + k];
        y1s[idx] = eluf(s);
    }

    float acc2[2][4][4];
#pragma unroll
    for (int uu = 0; uu < 2; uu++)
#pragma unroll
        for (int a = 0; a < 4; a++)
#pragma unroll
            for (int c = 0; c < 4; c++) acc2[uu][a][c] = 0.0f;

    for (int cig = 0; cig < 4; cig++) {
        __syncthreads();
        for (int idx = t; idx < 3584; idx += 256) {
            int co = idx / 56, rem = idx - co * 56;
            w2s[co * 57 + rem] = w2[co * 224 + cig * 56 + rem];
        }
        __syncthreads();
#pragma unroll
        for (int uu = 0; uu < 2; uu++) {
            int u = t + uu * 256;
            if (u >= 448) break;
            int p = u % 7;
            int cog = (u / 7) & 15;
            int bg = u / 112;
            int bb0 = bg * 4, co0 = cog * 4;
            for (int cil = 0; cil < 8; cil++) {
                int ci = cig * 8 + cil;
                float yv[4][7];
#pragma unroll
                for (int a = 0; a < 4; a++)
#pragma unroll
                    for (int k = 0; k < 7; k++)
                        yv[a][k] = y1s[(bb0 + a) * 416 + ci * 13 + p + k];
#pragma unroll
                for (int c = 0; c < 4; c++)
#pragma unroll
                    for (int k = 0; k < 7; k++) {
                        float wv = w2s[(co0 + c) * 57 + cil * 7 + k];
#pragma unroll
                        for (int a = 0; a < 4; a++) acc2[uu][a][c] += yv[a][k] * wv;
                    }
            }
        }
    }
    __syncthreads();
#pragma unroll
    for (int uu = 0; uu < 2; uu++) {
        int u = t + uu * 256;
        if (u >= 448) break;
        int p = u % 7;
        int cog = (u / 7) & 15;
        int bg = u / 112;
        int bb0 = bg * 4, co0 = cog * 4;
#pragma unroll
        for (int a = 0; a < 4; a++)
#pragma unroll
            for (int c = 0; c < 4; c++) {
                float s = acc2[uu][a][c] + b2[co0 + c];
                y2s[(bb0 + a) * 448 + (co0 + c) * 7 + p] = eluf(s);
            }
    }

    const int co0 = (t & 31) * 4;
    const int bb0 = (t >> 5) * 2;
    float acc3[2][4];
#pragma unroll
    for (int a = 0; a < 2; a++)
#pragma unroll
        for (int c = 0; c < 4; c++) acc3[a][c] = 0.0f;

    for (int ch = 0; ch < 7; ch++) {
        int ic = ch * 64;
        __syncthreads();
        for (int idx = t; idx < 8192; idx += 256) {
            int co = idx >> 6, ii = idx & 63;
            w3c[ii * 129 + co] = w3[co * 448 + ic + ii];
        }
        __syncthreads();
#pragma unroll 4
        for (int ii = 0; ii < 64; ii++) {
            float wv0 = w3c[ii * 129 + co0 + 0];
            float wv1 = w3c[ii * 129 + co0 + 1];
            float wv2 = w3c[ii * 129 + co0 + 2];
            float wv3 = w3c[ii * 129 + co0 + 3];
#pragma unroll
            for (int a = 0; a < 2; a++) {
                float yv = y2s[(bb0 + a) * 448 + ic + ii];
                acc3[a][0] += yv * wv0;
                acc3[a][1] += yv * wv1;
                acc3[a][2] += yv * wv2;
                acc3[a][3] += yv * wv3;
            }
        }
    }
#pragma unroll
    for (int a = 0; a < 2; a++)
#pragma unroll
        for (int c = 0; c < 4; c++) {
            float s = acc3[a][c] + b3[co0 + c];
            g_feat[(size_t)(b0 + bb0 + a) * 128 + co0 + c] = eluf(s);
        }
}

// ---------------- fp16 LSTM-cell GEMM core (half-N CTA) ----------------
#define SMEM_LSTM_WORDS 18048
#define SMEM_LSTM_BYTES (SMEM_LSTM_WORDS * 4)
#define AOFF 12288
#define BIASO 16640
#define HWO  16896

__device__ __forceinline__ void lstm_core(
    int blk, float* sm, uint32_t smb,
    const float* __restrict__ A0, int lda0, int k0len,
    const float* __restrict__ A1, int k1len,
    const uint32_t* __restrict__ Wp, const float* __restrict__ biasp,
    const float* __restrict__ Cprev, float* __restrict__ Hout, float* __restrict__ Cout,
    const float* __restrict__ h2head, const float* __restrict__ headW,
    const float* __restrict__ headB, float* __restrict__ outPrev)
{
    uint32_t* smw = (uint32_t*)sm;
    float* bias_s = sm + BIASO;
    float* hw_s   = sm + HWO;

    const int tid  = threadIdx.x;
    const int wid  = tid >> 5;
    const int lane = tid & 31;
    const int g    = lane >> 2;
    const int t4   = lane & 3;
    const int wm   = wid & 1;
    const int wn2  = wid >> 1;
    const int half = blk & 1;
    const int row0 = (blk >> 1) * 64;
    const int ar   = tid >> 3;
    const int aq   = tid & 7;

    bias_s[tid] = biasp[half * 256 + tid];
    if (h2head) {
        for (int idx = tid; idx < 1152; idx += 256) {
            int j = idx / 9, o = idx - j * 9;
            hw_s[idx] = headW[o * 128 + j];
        }
    }
    __syncthreads();

    float acc[2][8][4];
#pragma unroll
    for (int mt = 0; mt < 2; mt++)
#pragma unroll
        for (int j8 = 0; j8 < 8; j8++)
#pragma unroll
            for (int q = 0; q < 4; q++) acc[mt][j8][q] = 0.0f;

    const int nch = (k0len + k1len) >> 5;
    const int awsw = (2 * aq) ^ (2 * (ar & 7));

    // rotating buffer pointers (ring of 3, no % in loop)
    const uint32_t* aw0 = smw + AOFF;
    const uint32_t* aw1 = aw0 + 1024;
    const uint32_t* aw2 = aw1 + 1024;
    const uint4* bq0 = (const uint4*)(smw) + wn2 * 256;
    const uint4* bq1 = (const uint4*)(smw + 4096) + wn2 * 256;
    const uint4* bq2 = (const uint4*)(smw + 8192) + wn2 * 256;
    uint32_t* sp0 = smw + AOFF + ar * 16 + awsw;
    uint32_t* sp1 = sp0 + 1024;
    uint32_t* sp2 = sp1 + 1024;
    uint32_t bb0 = smb + (uint32_t)tid * 16u;
    uint32_t bb1 = bb0 + 16384u;
    uint32_t bb2 = bb1 + 16384u;

    auto ldgA = [&](int i, float4 v[2]) {
        int kb = i << 5;
        const float* src; int ld; int col;
        if (kb < k0len) { src = A0; ld = lda0; col = kb; }
        else            { src = A1; ld = 128;  col = kb - k0len; }
        v[0] = *(const float4*)(src + (size_t)(row0 + ar) * ld + col + aq * 4);
        v[1] = *(const float4*)(src + (size_t)(row0 + ar + 32) * ld + col + aq * 4);
    };
    auto stsA = [&](uint32_t* p, const float4 v[2]) {
        p[0]   = pack_h2(v[0].x, v[0].y);
        p[1]   = pack_h2(v[0].z, v[0].w);
        p[512] = pack_h2(v[1].x, v[1].y);
        p[513] = pack_h2(v[1].z, v[1].w);
    };
    auto issueB = [&](int i, uint32_t bb) {
        const uint32_t* wsrc = Wp + (size_t)(i * 2 + half) * 4096;
#pragma unroll
        for (int it = 0; it < 4; it++) {
            CP16(bb + (uint32_t)it * 4096u, wsrc + (size_t)(it * 256 + tid) * 4);
        }
        CP_COMMIT();
    };

    // prologue
    float4 hold[2];
    {
        float4 a0v[2];
        ldgA(0, a0v);
        stsA(sp0, a0v);
        issueB(0, bb0);
        if (nch > 1) { ldgA(1, hold); issueB(1, bb1); }
    }

    const int xg = 2 * g;
    const int r0a = wm * 32 + g;
    for (int i = 0; i < nch; i++) {
        if (i == nch - 1) { CP_WAIT0(); } else { CP_WAIT1(); }
        __syncthreads();
        if (i + 1 < nch) stsA(sp1, hold);
        if (i + 2 < nch) { ldgA(i + 2, hold); issueB(i + 2, bb2); }

        const uint32_t* Aw = aw0;
        const uint4*    Bq = bq0;

#pragma unroll
        for (int s = 0; s < 2; s++) {
            uint4 bv[4];
#pragma unroll
            for (int jp = 0; jp < 4; jp++) bv[jp] = Bq[s * 128 + jp * 32 + lane];
            uint32_t a[2][4];
#pragma unroll
            for (int mt = 0; mt < 2; mt++) {
                int r0 = r0a + mt * 16;
                int w0 = (s * 8 + t4) ^ xg;
                int w1 = (s * 8 + 4 + t4) ^ xg;
                a[mt][0] = Aw[r0 * 16 + w0];
                a[mt][1] = Aw[(r0 + 8) * 16 + w0];
                a[mt][2] = Aw[r0 * 16 + w1];
                a[mt][3] = Aw[(r0 + 8) * 16 + w1];
            }
#pragma unroll
            for (int jp = 0; jp < 4; jp++) {
                MMA_F16(acc[0][2 * jp],     a[0], bv[jp].x, bv[jp].y);
                MMA_F16(acc[1][2 * jp],     a[1], bv[jp].x, bv[jp].y);
                MMA_F16(acc[0][2 * jp + 1], a[0], bv[jp].z, bv[jp].w);
                MMA_F16(acc[1][2 * jp + 1], a[1], bv[jp].z, bv[jp].w);
            }
        }
        // rotate rings
        { const uint32_t* t0 = aw0; aw0 = aw1; aw1 = aw2; aw2 = t0; }
        { const uint4* t0 = bq0; bq0 = bq1; bq1 = bq2; bq2 = t0; }
        { uint32_t* t0 = sp0; sp0 = sp1; sp1 = sp2; sp2 = t0; }
        { uint32_t t0 = bb0; bb0 = bb1; bb1 = bb2; bb2 = t0; }
    }
    __syncthreads();

    // stage gates to [64][260]
#pragma unroll
    for (int mt = 0; mt < 2; mt++) {
        int row = wm * 32 + mt * 16 + g;
#pragma unroll
        for (int j8 = 0; j8 < 8; j8++) {
            int col = wn2 * 64 + j8 * 8 + 2 * t4;
            sm[row * 260 + col]           = acc[mt][j8][0];
            sm[row * 260 + col + 1]       = acc[mt][j8][1];
            sm[(row + 8) * 260 + col]     = acc[mt][j8][2];
            sm[(row + 8) * 260 + col + 1] = acc[mt][j8][3];
        }
    }
    __syncthreads();

    // cell epilogue
    {
        const int j0 = tid & 63;
        const int rg = tid >> 6;
        const int col = half * 64 + j0;
        const float4 bb = *(const float4*)(bias_s + 4 * j0);
#pragma unroll
        for (int rr = 0; rr < 16; rr++) {
            int r = rg * 16 + rr;
            int row = row0 + r;
            float4 gv = *(const float4*)(sm + r * 260 + 4 * j0);
            float gi = gv.x + bb.x;
            float gf = gv.y + bb.y;
            float gg = gv.z + bb.z;
            float go = gv.w + bb.w;
            float cp = Cprev ? Cprev[(size_t)row * 128 + col] : 0.0f;
            float c  = sigf(gf) * cp + sigf(gi) * tanhx(gg);
            float h  = sigf(go) * tanhx(c);
            Cout[(size_t)row * 128 + col] = c;
            Hout[(size_t)row * 128 + col] = h;
        }
    }

    // head for an older step's h2 (32 rows per CTA)
    if (h2head) {
        __syncthreads();
        const int hr0 = row0 + half * 32;
#pragma unroll
        for (int it = 0; it < 4; it++) {
            int idx = tid + it * 256;
            int r = idx >> 5, cq = idx & 31;
            float4 v = *(const float4*)(h2head + (size_t)(hr0 + r) * 128 + cq * 4);
            sm[r * 132 + cq * 4]     = v.x;
            sm[r * 132 + cq * 4 + 1] = v.y;
            sm[r * 132 + cq * 4 + 2] = v.z;
            sm[r * 132 + cq * 4 + 3] = v.w;
        }
        __syncthreads();
        for (int idx = tid; idx < 288; idx += 256) {
            int r = idx / 9, o = idx - r * 9;
            float s = headB[o];
            const float* hr = sm + r * 132;
#pragma unroll 8
            for (int jj = 0; jj < 128; jj++) s += hr[jj] * hw_s[jj * 9 + o];
            outPrev[(size_t)(hr0 + r) * 9 + o] = s;
        }
    }
}

// single-role kernel (step0 L1, final L2)
__global__ __launch_bounds__(256, 2)
void lstm_single_kernel(const float* __restrict__ A0, int lda0, int k0len,
                        const float* __restrict__ A1, int k1len,
                        const uint32_t* __restrict__ Wp, const float* __restrict__ biasp,
                        const float* __restrict__ Cprev,
                        float* __restrict__ Hout, float* __restrict__ Cout)
{
    extern __shared__ float sm[];
    uint32_t smb = smem_u32(sm);
    lstm_core(blockIdx.x, sm, smb, A0, lda0, k0len, A1, k1len, Wp, biasp,
              Cprev, Hout, Cout, nullptr, nullptr, nullptr, nullptr);
}

// merged: blocks [0,1024) = L1 of step s; [1024,2048) = L2 of step s-1
__global__ __launch_bounds__(256, 2)
void lstm_merged_kernel(const float* __restrict__ a0_1, const float* __restrict__ a1_1,
                        const uint32_t* __restrict__ W_1, const float* __restrict__ b_1,
                        const float* __restrict__ cp_1,
                        float* __restrict__ ho_1, float* __restrict__ co_1,
                        const float* __restrict__ h2head, const float* __restrict__ headW,
                        const float* __restrict__ headB, float* __restrict__ outPrev,
                        const float* __restrict__ a0_2, const float* __restrict__ a1_2, int k1_2,
                        const uint32_t* __restrict__ W_2, const float* __restrict__ b_2,
                        const float* __restrict__ cp_2,
                        float* __restrict__ ho_2, float* __restrict__ co_2)
{
    extern __shared__ float sm[];
    uint32_t smb = smem_u32(sm);
    if (blockIdx.x < 1024) {
        lstm_core(blockIdx.x, sm, smb, a0_1, 256, 256, a1_1, 128, W_1, b_1,
                  cp_1, ho_1, co_1, h2head, headW, headB, outPrev);
    } else {
        lstm_core(blockIdx.x - 1024, sm, smb, a0_2, 128, 128, a1_2, k1_2, W_2, b_2,
                  cp_2, ho_2, co_2, nullptr, nullptr, nullptr, nullptr);
    }
}

// ---------------- final head kernel: steps 15 and 16 ----------------
__global__ __launch_bounds__(256)
void head2_kernel(const float* __restrict__ h2a, const float* __restrict__ h2b,
                  const float* __restrict__ headW, const float* __restrict__ headB,
                  float* __restrict__ outA, float* __restrict__ outB)
{
    __shared__ float hs[64 * 132];
    __shared__ float hw[1152];
    const int t = threadIdx.x;
    const bool second = blockIdx.x >= 512;
    const float* h2 = second ? h2b : h2a;
    float* outp = second ? outB : outA;
    const int r0 = (second ? (blockIdx.x - 512) : blockIdx.x) * 64;
    for (int idx = t; idx < 1152; idx += 256) {
        int j = idx / 9, o = idx - j * 9;
        hw[idx] = headW[o * 128 + j];
    }
#pragma unroll
    for (int it = 0; it < 8; it++) {
        int idx = t + it * 256;
        int r = idx >> 5, cq = idx & 31;
        float4 v = *(const float4*)(h2 + (size_t)(r0 + r) * 128 + cq * 4);
        hs[r * 132 + cq * 4]     = v.x;
        hs[r * 132 + cq * 4 + 1] = v.y;
        hs[r * 132 + cq * 4 + 2] = v.z;
        hs[r * 132 + cq * 4 + 3] = v.w;
    }
    __syncthreads();
    for (int idx = t; idx < 576; idx += 256) {
        int r = idx / 9, o = idx - r * 9;
        float s = headB[o];
        const float* hr = hs + r * 132;
#pragma unroll 8
        for (int jj = 0; jj < 128; jj++) s += hr[jj] * hw[jj * 9 + o];
        outp[(size_t)(r0 + r) * 9 + o] = s;
    }
}

// ---------------- launch ----------------
extern "C" void kernel_launch(void* const* d_in, const int* in_sizes, int n_in,
                              void* d_out, int out_size) {
    const float* x        = (const float*)d_in[0];
    const float* ps       = (const float*)d_in[1];
    const float* conv1_w  = (const float*)d_in[2];
    const float* conv1_b  = (const float*)d_in[3];
    const float* conv2_w  = (const float*)d_in[4];
    const float* conv2_b  = (const float*)d_in[5];
    const float* conv3_w  = (const float*)d_in[6];
    const float* conv3_b  = (const float*)d_in[7];
    const float* w_ih1    = (const float*)d_in[8];
    const float* w_hh1    = (const float*)d_in[9];
    const float* b_ih1    = (const float*)d_in[10];
    const float* b_hh1    = (const float*)d_in[11];
    const float* w_ih2    = (const float*)d_in[12];
    const float* w_hh2    = (const float*)d_in[13];
    const float* b_ih2    = (const float*)d_in[14];
    const float* b_hh2    = (const float*)d_in[15];
    const float* head_w   = (const float*)d_in[16];
    const float* head_b   = (const float*)d_in[17];
    float* out = (float*)d_out;

    const int conv_smem = 26256 * 4;
    cudaFuncSetAttribute(conv_kernel, cudaFuncAttributeMaxDynamicSharedMemorySize, conv_smem);
    cudaFuncSetAttribute(lstm_single_kernel, cudaFuncAttributeMaxDynamicSharedMemorySize, SMEM_LSTM_BYTES);
    cudaFuncSetAttribute(lstm_merged_kernel, cudaFuncAttributeMaxDynamicSharedMemorySize, SMEM_LSTM_BYTES);

    float *feat, *h1, *c1, *h2, *c2, *b1p, *b2p;
    uint32_t *W1h, *W2h;
    cudaGetSymbolAddress((void**)&feat, g_feat);
    cudaGetSymbolAddress((void**)&h1, g_h1);
    cudaGetSymbolAddress((void**)&c1, g_c1);
    cudaGetSymbolAddress((void**)&h2, g_h2);
    cudaGetSymbolAddress((void**)&c2, g_c2);
    cudaGetSymbolAddress((void**)&W1h, g_W1h);
    cudaGetSymbolAddress((void**)&W2h, g_W2h);
    cudaGetSymbolAddress((void**)&b1p, g_b1p);
    cudaGetSymbolAddress((void**)&b2p, g_b2p);

    const int prep_total = 12 * 8192 + 8 * 8192 + 1024;
    prep_kernel<<<(prep_total + 255) / 256, 256>>>(w_ih1, w_hh1, b_ih1, b_hh1,
                                                   w_ih2, w_hh2, b_ih2, b_hh2);

    conv_kernel<<<Bn / 16, 256, conv_smem>>>(x, conv1_w, conv1_b, conv2_w, conv2_b,
                                             conv3_w, conv3_b);

    // L1_0: writes h1[0]
    lstm_single_kernel<<<1024, 256, SMEM_LSTM_BYTES>>>(
        feat, 128, 128, nullptr, 0, W1h, b1p, nullptr, h1, c1);

    // merged steps: launch s contains [L1_s | L2_{s-1}]
    for (int s = 1; s <= Tn; s++) {
        const float* A      = ps + (size_t)(s - 1) * Bn * 256;
        const float* h1prev = h1 + (size_t)((s - 1) & 1) * BH;
        float*       h1out  = h1 + (size_t)(s & 1) * BH;
        const float* h2old  = h2 + (size_t)(s & 1) * BH;        // h2_{s-2}, valid s>=2
        float*       h2out  = h2 + (size_t)((s - 1) & 1) * BH;  // h2_{s-1}
        lstm_merged_kernel<<<2048, 256, SMEM_LSTM_BYTES>>>(
            // L1_s
            A, h1prev, W1h, b1p, c1, h1out, c1,
            (s >= 2) ? h2old : nullptr, head_w, head_b,
            (s >= 2) ? (out + (size_t)(s - 2) * Bn * 9) : nullptr,
            // L2_{s-1}
            h1prev, (s >= 2) ? h2old : nullptr, (s >= 2) ? 128 : 0,
            W2h, b2p, (s >= 2) ? c2 : nullptr, h2out, c2);
    }

    // L2_16: h1_16 = h1[0], h2_15 = h2[1] -> writes h2[0]
    lstm_single_kernel<<<1024, 256, SMEM_LSTM_BYTES>>>(
        h1, 128, 128, h2 + BH, 128, W2h, b2p, c2, h2, c2);

    // heads for steps 15 (h2[1]) and 16 (h2[0])
    head2_kernel<<<1024, 256>>>(h2 + BH, h2, head_w, head_b,
                                out + (size_t)15 * Bn * 9, out + (size_t)16 * Bn * 9);
}

// round 11
// speedup vs baseline: 2.2198x; 1.1752x over previous
#include <cuda_runtime.h>
#include <cuda_fp16.h>
#include <math.h>
#include <stdint.h>

#define Bn 32768
#define Tn 16
#define BH (Bn * 128)

// ---------------- device scratch ----------------
__device__ float    g_feat[Bn * 128];
__device__ float    g_h1[2 * BH];
__device__ float    g_c1[BH];
__device__ float    g_h2[2 * BH];
__device__ float    g_c2[BH];
__device__ __align__(16) uint32_t g_W1h[12 * 8192];   // lstm L1 fragment-ordered half2
__device__ __align__(16) uint32_t g_W2h[8 * 8192];    // lstm L2
__device__ __align__(16) uint32_t g_W2c[7168];        // conv2 fragment-ordered half2
__device__ __align__(16) uint32_t g_W3c[32768];       // conv3 fragment-ordered half2
__device__ float    g_b1p[512];         // gate-interleaved n' = 4j+gate
__device__ float    g_b2p[512];

// ---------------- helpers ----------------
__device__ __forceinline__ uint32_t smem_u32(const void* p) {
    uint32_t r;
    asm("{ .reg .u64 t; cvta.to.shared.u64 t, %1; cvt.u32.u64 %0, t; }" : "=r"(r) : "l"(p));
    return r;
}
#define CP16(dst, src) asm volatile("cp.async.cg.shared.global [%0], [%1], 16;" :: "r"(dst), "l"(src))
#define CP_COMMIT()    asm volatile("cp.async.commit_group;" ::: "memory")
#define CP_WAIT0()     asm volatile("cp.async.wait_group 0;" ::: "memory")
#define CP_WAIT1()     asm volatile("cp.async.wait_group 1;" ::: "memory")

#define MMA_F16(d, a, b0v, b1v) \
    asm volatile("mma.sync.aligned.m16n8k16.row.col.f32.f16.f16.f32 " \
        "{%0,%1,%2,%3}, {%4,%5,%6,%7}, {%8,%9}, {%0,%1,%2,%3};" \
        : "+f"((d)[0]), "+f"((d)[1]), "+f"((d)[2]), "+f"((d)[3]) \
        : "r"((a)[0]), "r"((a)[1]), "r"((a)[2]), "r"((a)[3]), "r"(b0v), "r"(b1v))

__device__ __forceinline__ uint32_t pack_h2(float lo, float hi) {
    __half2 h = __floats2half2_rn(lo, hi);
    uint32_t u;
    memcpy(&u, &h, 4);
    return u;
}
__device__ __forceinline__ float sigf(float x) { return __fdividef(1.0f, 1.0f + __expf(-x)); }
__device__ __forceinline__ float tanhx(float x) { return __fdividef(2.0f, 1.0f + __expf(-2.0f * x)) - 1.0f; }
__device__ __forceinline__ float eluf(float x) { return x > 0.0f ? x : expm1f(x); }

// ---------------- weight prep ----------------
__global__ void prep_kernel(const float* __restrict__ w_ih1, const float* __restrict__ w_hh1,
                            const float* __restrict__ b_ih1, const float* __restrict__ b_hh1,
                            const float* __restrict__ w_ih2, const float* __restrict__ w_hh2,
                            const float* __restrict__ b_ih2, const float* __restrict__ b_hh2,
                            const float* __restrict__ w2c, const float* __restrict__ w3c) {
    int i = blockIdx.x * blockDim.x + threadIdx.x;
    const int total1 = 12 * 8192;
    const int total2 = 8 * 8192;
    const int base3  = total1 + total2 + 1024;
    if (i < total1 + total2) {
        int li = (i < total1) ? i : i - total1;
        int w    = li & 3;
        int lane = (li >> 2) & 31;
        int jp   = (li >> 7) & 3;
        int s    = (li >> 9) & 1;
        int wn2  = (li >> 10) & 3;
        int half = (li >> 12) & 1;
        int ch   = li >> 13;
        int g = lane >> 2, t4 = lane & 3;
        int j8 = jp * 2 + (w >> 1);
        int k  = ch * 32 + s * 16 + 8 * (w & 1) + 2 * t4;
        int np = half * 256 + wn2 * 64 + j8 * 8 + g;
        int j = np >> 2, gate = np & 3;
        int n = gate * 128 + j;
        float f0, f1;
        if (i < total1) {
            if (k < 256) { f0 = w_ih1[n * 256 + k];        f1 = w_ih1[n * 256 + k + 1]; }
            else         { f0 = w_hh1[n * 128 + k - 256];  f1 = w_hh1[n * 128 + k - 255]; }
            g_W1h[li] = pack_h2(f0, f1);
        } else {
            if (k < 128) { f0 = w_ih2[n * 128 + k];        f1 = w_ih2[n * 128 + k + 1]; }
            else         { f0 = w_hh2[n * 128 + k - 128];  f1 = w_hh2[n * 128 + k - 127]; }
            g_W2h[li] = pack_h2(f0, f1);
        }
    } else if (i < total1 + total2 + 512) {
        int np = i - total1 - total2;
        int j = np >> 2, gate = np & 3;
        int n = gate * 128 + j;
        g_b1p[np] = b_ih1[n] + b_hh1[n];
    } else if (i < base3) {
        int np = i - total1 - total2 - 512;
        int j = np >> 2, gate = np & 3;
        int n = gate * 128 + j;
        g_b2p[np] = b_ih2[n] + b_hh2[n];
    } else if (i < base3 + 7168) {
        // conv2 weights: word = ((sc)*8 + j8)*64 + lane*2 + w01, sc = ch*2+s < 14
        int wi = i - base3;
        int w01  = wi & 1;
        int lane = (wi >> 1) & 31;
        int j8   = (wi >> 6) & 7;
        int sc   = wi >> 9;
        int g = lane >> 2, t4 = lane & 3;
        int n = j8 * 8 + g;
        int k0 = sc * 16 + 2 * t4 + 8 * w01;
        g_W2c[wi] = pack_h2(w2c[n * 224 + k0], w2c[n * 224 + k0 + 1]);
    } else if (i < base3 + 7168 + 32768) {
        // conv3 weights: word = ((sc)*16 + j8)*64 + lane*2 + w01, sc = ch*2+s < 32
        int wi = i - base3 - 7168;
        int w01  = wi & 1;
        int lane = (wi >> 1) & 31;
        int j8   = (wi >> 6) & 15;
        int sc   = wi >> 10;
        int g = lane >> 2, t4 = lane & 3;
        int n = j8 * 8 + g;
        int k0 = sc * 16 + 2 * t4 + 8 * w01;
        float f0, f1;
        {
            int ci2 = k0 >> 3, p = k0 & 7;
            f0 = (p < 7) ? w3c[n * 448 + ci2 * 7 + p] : 0.0f;
        }
        {
            int k1 = k0 + 1;
            int ci2 = k1 >> 3, p = k1 & 7;
            f1 = (p < 7) ? w3c[n * 448 + ci2 * 7 + p] : 0.0f;
        }
        g_W3c[wi] = pack_h2(f0, f1);
    }
}

// ---------------- conv stack: scalar conv1 + MMA conv2/conv3 ----------------
// smem word offsets
#define CXS   0       // 640
#define CW2F  640     // 7168
#define CB2S  7808    // 64
#define CB3S  7872    // 128
#define CA3W  8000    // 8192  (16 chunks x 32 rows x 16 words)
#define CW3R  16192   // 2 x 2048
#define CY1H  20288   // 6656  (32 x 416 halves = 13312 halves)
#define CA2W  26944   // 28672 (7 chunks x 256 rows x 16 words)
#define CW1S  55616   // 224
#define CB1S  55840   // 32
#define CONV_SMEM_WORDS 55872
#define CONV_SMEM_BYTES (CONV_SMEM_WORDS * 4)

__global__ __launch_bounds__(256, 1)
void conv_kernel(const float* __restrict__ x,
                 const float* __restrict__ w1, const float* __restrict__ b1,
                 const float* __restrict__ b2, const float* __restrict__ b3) {
    extern __shared__ float sm[];
    __half* smh = (__half*)sm;
    uint32_t* smw = (uint32_t*)sm;
    uint32_t smb = smem_u32(sm);

    const int t    = threadIdx.x;
    const int lane = t & 31;
    const int wid  = t >> 5;
    const int g    = lane >> 2;
    const int t4   = lane & 3;
    const int b0g  = blockIdx.x * 32;

    // stream conv2 weight frags (28KB, one group)
#pragma unroll
    for (int it = 0; it < 7; it++) {
        int gi = it * 1024 + t * 4;
        CP16(smb + (CW2F + gi) * 4, g_W2c + gi);
    }
    CP_COMMIT();

    // scalar loads
    for (int idx = t; idx < 608; idx += 256) {
        int b = idx / 19, q = idx - b * 19;
        sm[CXS + b * 20 + q] = x[(size_t)(b0g + b) * 19 + q];
    }
    if (t < 224) sm[CW1S + t] = w1[t];
    if (t < 32)  sm[CB1S + t] = b1[t];
    if (t < 64)  sm[CB2S + t] = b2[t];
    if (t < 128) sm[CB3S + t] = b3[t];
    __syncthreads();

    // conv1 -> y1h fp16 (32b x 32ci x 13q)
    for (int idx = t; idx < 13312; idx += 256) {
        int b = idx / 416;
        int rem = idx - b * 416;
        int ci = rem / 13, q = rem - ci * 13;
        float s = sm[CB1S + ci];
#pragma unroll
        for (int k = 0; k < 7; k++) s += sm[CXS + b * 20 + q + k] * sm[CW1S + ci * 7 + k];
        smh[CY1H * 2 + idx] = __float2half(eluf(s));
    }
    // zero A3
    for (int idx = t; idx < 8192; idx += 256) sm[CA3W + idx] = 0.0f;
    __syncthreads();

    // A2 build: thread = row r (r = b*8+p), fragment-swizzled fp16
    {
        const int r = t;
        const int b = r >> 3, p = r & 7;
        const int xr = 2 * (r & 7);
        if (p < 7) {
            const __half* y1r = smh + CY1H * 2 + b * 416 + p;
            int c = 0;
            for (int ci = 0; ci < 32; ci++) {
                const __half* yq = y1r + ci * 13;
#pragma unroll
                for (int k = 0; k < 7; k++, c++) {
                    int ch = c >> 5, hc = c & 31;
                    int phys = (hc >> 1) ^ xr;
                    smh[(CA2W + ch * 4096 + r * 16 + phys) * 2 + (hc & 1)] = yq[k];
                }
            }
        } else {
            const __half z = __float2half(0.0f);
            for (int c = 0; c < 224; c++) {
                int ch = c >> 5, hc = c & 31;
                int phys = (hc >> 1) ^ xr;
                smh[(CA2W + ch * 4096 + r * 16 + phys) * 2 + (hc & 1)] = z;
            }
        }
    }
    CP_WAIT0();   // w2f ready
    __syncthreads();

    // kick conv3 weight chunks 0,1
    auto issueW3 = [&](int i) {
        const uint32_t* src = g_W3c + i * 2048;
        uint32_t dst = smb + (CW3R + (i & 1) * 2048) * 4;
#pragma unroll
        for (int it = 0; it < 2; it++) {
            int gi = it * 1024 + t * 4;
            CP16(dst + gi * 4, src + gi);
        }
        CP_COMMIT();
    };
    issueW3(0);
    issueW3(1);

    // ---- GEMM2: M=256 (32b x 8p), N=64, K=224 ----
    const int wm2 = wid & 3;
    const int wn  = wid >> 2;
    float acc2[4][4][4];
#pragma unroll
    for (int mt = 0; mt < 4; mt++)
#pragma unroll
        for (int jp = 0; jp < 4; jp++)
#pragma unroll
            for (int q = 0; q < 4; q++) acc2[mt][jp][q] = 0.0f;

    for (int ch = 0; ch < 7; ch++) {
        const uint32_t* Ab = smw + CA2W + ch * 4096;
#pragma unroll
        for (int s = 0; s < 2; s++) {
            uint2 bf[4];
#pragma unroll
            for (int jp = 0; jp < 4; jp++) {
                int j8 = wn * 4 + jp;
                bf[jp] = *(const uint2*)(smw + CW2F + ((ch * 2 + s) * 8 + j8) * 64 + lane * 2);
            }
            int w0  = (s * 8 + t4) ^ (2 * g);
            int w1i = (s * 8 + 4 + t4) ^ (2 * g);
#pragma unroll
            for (int mt = 0; mt < 4; mt++) {
                int r0 = wm2 * 64 + mt * 16;
                uint32_t a[4];
                a[0] = Ab[(r0 + g) * 16 + w0];
                a[1] = Ab[(r0 + g + 8) * 16 + w0];
                a[2] = Ab[(r0 + g) * 16 + w1i];
                a[3] = Ab[(r0 + g + 8) * 16 + w1i];
#pragma unroll
                for (int jp = 0; jp < 4; jp++)
                    MMA_F16(acc2[mt][jp], a, bf[jp].x, bf[jp].y);
            }
        }
    }

    // GEMM2 epilogue: ELU(out2 + b2) -> A3 fragment layout (K3 = co*8 + p)
#pragma unroll
    for (int mt = 0; mt < 4; mt++) {
#pragma unroll
        for (int q = 0; q < 4; q++) {
            int r = wm2 * 64 + mt * 16 + g + ((q >> 1) << 3);
            int p = r & 7;
            if (p == 7) continue;
            int b = r >> 3;
            int xr = 2 * (b & 7);
#pragma unroll
            for (int jp = 0; jp < 4; jp++) {
                int n = wn * 32 + jp * 8 + 2 * t4 + (q & 1);
                float v = eluf(acc2[mt][jp][q] + sm[CB2S + n]);
                int c3 = n * 8 + p;
                int ch3 = c3 >> 5, hc = c3 & 31;
                int phys = (hc >> 1) ^ xr;
                smh[(CA3W + ch3 * 512 + b * 16 + phys) * 2 + (hc & 1)] = __float2half(v);
            }
        }
    }
    __syncthreads();

    // ---- GEMM3: M=32, N=128, K=512 (16 chunks, w3 ring) ----
    const int wm3 = wid & 1;
    const int wn3 = wid >> 1;
    float acc3[4][4];
#pragma unroll
    for (int jp = 0; jp < 4; jp++)
#pragma unroll
        for (int q = 0; q < 4; q++) acc3[jp][q] = 0.0f;

    for (int i = 0; i < 16; i++) {
        if (i < 14) { CP_WAIT1(); } else { CP_WAIT0(); }
        __syncthreads();
        const uint32_t* Br = smw + CW3R + (i & 1) * 2048;
        const uint32_t* Ab = smw + CA3W + i * 512;
#pragma unroll
        for (int s = 0; s < 2; s++) {
            int w0  = (s * 8 + t4) ^ (2 * g);
            int w1i = (s * 8 + 4 + t4) ^ (2 * g);
            int r0 = wm3 * 16;
            uint32_t a[4];
            a[0] = Ab[(r0 + g) * 16 + w0];
            a[1] = Ab[(r0 + g + 8) * 16 + w0];
            a[2] = Ab[(r0 + g) * 16 + w1i];
            a[3] = Ab[(r0 + g + 8) * 16 + w1i];
#pragma unroll
            for (int jp = 0; jp < 4; jp++) {
                int j8 = wn3 * 4 + jp;
                uint2 bf = *(const uint2*)(Br + (s * 16 + j8) * 64 + lane * 2);
                MMA_F16(acc3[jp], a, bf.x, bf.y);
            }
        }
        __syncthreads();
        if (i + 2 < 16) issueW3(i + 2);
    }

    // GEMM3 epilogue -> g_feat
#pragma unroll
    for (int jp = 0; jp < 4; jp++) {
#pragma unroll
        for (int q = 0; q < 4; q++) {
            int r = wm3 * 16 + g + ((q >> 1) << 3);
            int col = wn3 * 32 + jp * 8 + 2 * t4 + (q & 1);
            g_feat[(size_t)(b0g + r) * 128 + col] = eluf(acc3[jp][q] + sm[CB3S + col]);
        }
    }
}

// ---------------- fp16 LSTM-cell GEMM core (half-N CTA) ----------------
#define SMEM_LSTM_WORDS 18048
#define SMEM_LSTM_BYTES (SMEM_LSTM_WORDS * 4)
#define AOFF 12288
#define BIASO 16640
#define HWO  16896

__device__ __forceinline__ void lstm_core(
    int blk, float* sm, uint32_t smb,
    const float* __restrict__ A0, int lda0, int k0len,
    const float* __restrict__ A1, int k1len,
    const uint32_t* __restrict__ Wp, const float* __restrict__ biasp,
    const float* __restrict__ Cprev, float* __restrict__ Hout, float* __restrict__ Cout,
    const float* __restrict__ h2head, const float* __restrict__ headW,
    const float* __restrict__ headB, float* __restrict__ outPrev)
{
    uint32_t* smw = (uint32_t*)sm;
    float* bias_s = sm + BIASO;
    float* hw_s   = sm + HWO;

    const int tid  = threadIdx.x;
    const int wid  = tid >> 5;
    const int lane = tid & 31;
    const int g    = lane >> 2;
    const int t4   = lane & 3;
    const int wm   = wid & 1;
    const int wn2  = wid >> 1;
    const int half = blk & 1;
    const int row0 = (blk >> 1) * 64;
    const int ar   = tid >> 3;
    const int aq   = tid & 7;

    bias_s[tid] = biasp[half * 256 + tid];
    if (h2head) {
        for (int idx = tid; idx < 1152; idx += 256) {
            int j = idx / 9, o = idx - j * 9;
            hw_s[idx] = headW[o * 128 + j];
        }
    }
    __syncthreads();

    float acc[2][8][4];
#pragma unroll
    for (int mt = 0; mt < 2; mt++)
#pragma unroll
        for (int j8 = 0; j8 < 8; j8++)
#pragma unroll
            for (int q = 0; q < 4; q++) acc[mt][j8][q] = 0.0f;

    const int nch = (k0len + k1len) >> 5;
    const int awsw = (2 * aq) ^ (2 * (ar & 7));

    const uint32_t* aw0 = smw + AOFF;
    const uint32_t* aw1 = aw0 + 1024;
    const uint32_t* aw2 = aw1 + 1024;
    const uint4* bq0 = (const uint4*)(smw) + wn2 * 256;
    const uint4* bq1 = (const uint4*)(smw + 4096) + wn2 * 256;
    const uint4* bq2 = (const uint4*)(smw + 8192) + wn2 * 256;
    uint32_t* sp0 = smw + AOFF + ar * 16 + awsw;
    uint32_t* sp1 = sp0 + 1024;
    uint32_t* sp2 = sp1 + 1024;
    uint32_t bb0 = smb + (uint32_t)tid * 16u;
    uint32_t bb1 = bb0 + 16384u;
    uint32_t bb2 = bb1 + 16384u;

    auto ldgA = [&](int i, float4 v[2]) {
        int kb = i << 5;
        const float* src; int ld; int col;
        if (kb < k0len) { src = A0; ld = lda0; col = kb; }
        else            { src = A1; ld = 128;  col = kb - k0len; }
        v[0] = *(const float4*)(src + (size_t)(row0 + ar) * ld + col + aq * 4);
        v[1] = *(const float4*)(src + (size_t)(row0 + ar + 32) * ld + col + aq * 4);
    };
    auto stsA = [&](uint32_t* p, const float4 v[2]) {
        p[0]   = pack_h2(v[0].x, v[0].y);
        p[1]   = pack_h2(v[0].z, v[0].w);
        p[512] = pack_h2(v[1].x, v[1].y);
        p[513] = pack_h2(v[1].z, v[1].w);
    };
    auto issueB = [&](int i, uint32_t bb) {
        const uint32_t* wsrc = Wp + (size_t)(i * 2 + half) * 4096;
#pragma unroll
        for (int it = 0; it < 4; it++) {
            CP16(bb + (uint32_t)it * 4096u, wsrc + (size_t)(it * 256 + tid) * 4);
        }
        CP_COMMIT();
    };

    float4 hold[2];
    {
        float4 a0v[2];
        ldgA(0, a0v);
        stsA(sp0, a0v);
        issueB(0, bb0);
        if (nch > 1) { ldgA(1, hold); issueB(1, bb1); }
    }

    const int xg = 2 * g;
    const int r0a = wm * 32 + g;
    for (int i = 0; i < nch; i++) {
        if (i == nch - 1) { CP_WAIT0(); } else { CP_WAIT1(); }
        __syncthreads();
        if (i + 1 < nch) stsA(sp1, hold);
        if (i + 2 < nch) { ldgA(i + 2, hold); issueB(i + 2, bb2); }

        const uint32_t* Aw = aw0;
        const uint4*    Bq = bq0;

#pragma unroll
        for (int s = 0; s < 2; s++) {
            uint4 bv[4];
#pragma unroll
            for (int jp = 0; jp < 4; jp++) bv[jp] = Bq[s * 128 + jp * 32 + lane];
            uint32_t a[2][4];
#pragma unroll
            for (int mt = 0; mt < 2; mt++) {
                int r0 = r0a + mt * 16;
                int w0 = (s * 8 + t4) ^ xg;
                int w1 = (s * 8 + 4 + t4) ^ xg;
                a[mt][0] = Aw[r0 * 16 + w0];
                a[mt][1] = Aw[(r0 + 8) * 16 + w0];
                a[mt][2] = Aw[r0 * 16 + w1];
                a[mt][3] = Aw[(r0 + 8) * 16 + w1];
            }
#pragma unroll
            for (int jp = 0; jp < 4; jp++) {
                MMA_F16(acc[0][2 * jp],     a[0], bv[jp].x, bv[jp].y);
                MMA_F16(acc[1][2 * jp],     a[1], bv[jp].x, bv[jp].y);
                MMA_F16(acc[0][2 * jp + 1], a[0], bv[jp].z, bv[jp].w);
                MMA_F16(acc[1][2 * jp + 1], a[1], bv[jp].z, bv[jp].w);
            }
        }
        { const uint32_t* t0 = aw0; aw0 = aw1; aw1 = aw2; aw2 = t0; }
        { const uint4* t0 = bq0; bq0 = bq1; bq1 = bq2; bq2 = t0; }
        { uint32_t* t0 = sp0; sp0 = sp1; sp1 = sp2; sp2 = t0; }
        { uint32_t t0 = bb0; bb0 = bb1; bb1 = bb2; bb2 = t0; }
    }
    __syncthreads();

#pragma unroll
    for (int mt = 0; mt < 2; mt++) {
        int row = wm * 32 + mt * 16 + g;
#pragma unroll
        for (int j8 = 0; j8 < 8; j8++) {
            int col = wn2 * 64 + j8 * 8 + 2 * t4;
            sm[row * 260 + col]           = acc[mt][j8][0];
            sm[row * 260 + col + 1]       = acc[mt][j8][1];
            sm[(row + 8) * 260 + col]     = acc[mt][j8][2];
            sm[(row + 8) * 260 + col + 1] = acc[mt][j8][3];
        }
    }
    __syncthreads();

    {
        const int j0 = tid & 63;
        const int rg = tid >> 6;
        const int col = half * 64 + j0;
        const float4 bb = *(const float4*)(bias_s + 4 * j0);
#pragma unroll
        for (int rr = 0; rr < 16; rr++) {
            int r = rg * 16 + rr;
            int row = row0 + r;
            float4 gv = *(const float4*)(sm + r * 260 + 4 * j0);
            float gi = gv.x + bb.x;
            float gf = gv.y + bb.y;
            float gg = gv.z + bb.z;
            float go = gv.w + bb.w;
            float cp = Cprev ? Cprev[(size_t)row * 128 + col] : 0.0f;
            float c  = sigf(gf) * cp + sigf(gi) * tanhx(gg);
            float h  = sigf(go) * tanhx(c);
            Cout[(size_t)row * 128 + col] = c;
            Hout[(size_t)row * 128 + col] = h;
        }
    }

    if (h2head) {
        __syncthreads();
        const int hr0 = row0 + half * 32;
#pragma unroll
        for (int it = 0; it < 4; it++) {
            int idx = tid + it * 256;
            int r = idx >> 5, cq = idx & 31;
            float4 v = *(const float4*)(h2head + (size_t)(hr0 + r) * 128 + cq * 4);
            sm[r * 132 + cq * 4]     = v.x;
            sm[r * 132 + cq * 4 + 1] = v.y;
            sm[r * 132 + cq * 4 + 2] = v.z;
            sm[r * 132 + cq * 4 + 3] = v.w;
        }
        __syncthreads();
        for (int idx = tid; idx < 288; idx += 256) {
            int r = idx / 9, o = idx - r * 9;
            float s = headB[o];
            const float* hr = sm + r * 132;
#pragma unroll 8
            for (int jj = 0; jj < 128; jj++) s += hr[jj] * hw_s[jj * 9 + o];
            outPrev[(size_t)(hr0 + r) * 9 + o] = s;
        }
    }
}

__global__ __launch_bounds__(256, 2)
void lstm_single_kernel(const float* __restrict__ A0, int lda0, int k0len,
                        const float* __restrict__ A1, int k1len,
                        const uint32_t* __restrict__ Wp, const float* __restrict__ biasp,
                        const float* __restrict__ Cprev,
                        float* __restrict__ Hout, float* __restrict__ Cout)
{
    extern __shared__ float sm[];
    uint32_t smb = smem_u32(sm);
    lstm_core(blockIdx.x, sm, smb, A0, lda0, k0len, A1, k1len, Wp, biasp,
              Cprev, Hout, Cout, nullptr, nullptr, nullptr, nullptr);
}

__global__ __launch_bounds__(256, 2)
void lstm_merged_kernel(const float* __restrict__ a0_1, const float* __restrict__ a1_1,
                        const uint32_t* __restrict__ W_1, const float* __restrict__ b_1,
                        const float* __restrict__ cp_1,
                        float* __restrict__ ho_1, float* __restrict__ co_1,
                        const float* __restrict__ h2head, const float* __restrict__ headW,
                        const float* __restrict__ headB, float* __restrict__ outPrev,
                        const float* __restrict__ a0_2, const float* __restrict__ a1_2, int k1_2,
                        const uint32_t* __restrict__ W_2, const float* __restrict__ b_2,
                        const float* __restrict__ cp_2,
                        float* __restrict__ ho_2, float* __restrict__ co_2)
{
    extern __shared__ float sm[];
    uint32_t smb = smem_u32(sm);
    if (blockIdx.x < 1024) {
        lstm_core(blockIdx.x, sm, smb, a0_1, 256, 256, a1_1, 128, W_1, b_1,
                  cp_1, ho_1, co_1, h2head, headW, headB, outPrev);
    } else {
        lstm_core(blockIdx.x - 1024, sm, smb, a0_2, 128, 128, a1_2, k1_2, W_2, b_2,
                  cp_2, ho_2, co_2, nullptr, nullptr, nullptr, nullptr);
    }
}

// ---------------- final head kernel: steps 15 and 16 ----------------
__global__ __launch_bounds__(256)
void head2_kernel(const float* __restrict__ h2a, const float* __restrict__ h2b,
                  const float* __restrict__ headW, const float* __restrict__ headB,
                  float* __restrict__ outA, float* __restrict__ outB)
{
    __shared__ float hs[64 * 132];
    __shared__ float hw[1152];
    const int t = threadIdx.x;
    const bool second = blockIdx.x >= 512;
    const float* h2 = second ? h2b : h2a;
    float* outp = second ? outB : outA;
    const int r0 = (second ? (blockIdx.x - 512) : blockIdx.x) * 64;
    for (int idx = t; idx < 1152; idx += 256) {
        int j = idx / 9, o = idx - j * 9;
        hw[idx] = headW[o * 128 + j];
    }
#pragma unroll
    for (int it = 0; it < 8; it++) {
        int idx = t + it * 256;
        int r = idx >> 5, cq = idx & 31;
        float4 v = *(const float4*)(h2 + (size_t)(r0 + r) * 128 + cq * 4);
        hs[r * 132 + cq * 4]     = v.x;
        hs[r * 132 + cq * 4 + 1] = v.y;
        hs[r * 132 + cq * 4 + 2] = v.z;
        hs[r * 132 + cq * 4 + 3] = v.w;
    }
    __syncthreads();
    for (int idx = t; idx < 576; idx += 256) {
        int r = idx / 9, o = idx - r * 9;
        float s = headB[o];
        const float* hr = hs + r * 132;
#pragma unroll 8
        for (int jj = 0; jj < 128; jj++) s += hr[jj] * hw[jj * 9 + o];
        outp[(size_t)(r0 + r) * 9 + o] = s;
    }
}

// ---------------- launch ----------------
extern "C" void kernel_launch(void* const* d_in, const int* in_sizes, int n_in,
                              void* d_out, int out_size) {
    const float* x        = (const float*)d_in[0];
    const float* ps       = (const float*)d_in[1];
    const float* conv1_w  = (const float*)d_in[2];
    const float* conv1_b  = (const float*)d_in[3];
    const float* conv2_w  = (const float*)d_in[4];
    const float* conv2_b  = (const float*)d_in[5];
    const float* conv3_w  = (const float*)d_in[6];
    const float* conv3_b  = (const float*)d_in[7];
    const float* w_ih1    = (const float*)d_in[8];
    const float* w_hh1    = (const float*)d_in[9];
    const float* b_ih1    = (const float*)d_in[10];
    const float* b_hh1    = (const float*)d_in[11];
    const float* w_ih2    = (const float*)d_in[12];
    const float* w_hh2    = (const float*)d_in[13];
    const float* b_ih2    = (const float*)d_in[14];
    const float* b_hh2    = (const float*)d_in[15];
    const float* head_w   = (const float*)d_in[16];
    const float* head_b   = (const float*)d_in[17];
    float* out = (float*)d_out;

    cudaFuncSetAttribute(conv_kernel, cudaFuncAttributeMaxDynamicSharedMemorySize, CONV_SMEM_BYTES);
    cudaFuncSetAttribute(lstm_single_kernel, cudaFuncAttributeMaxDynamicSharedMemorySize, SMEM_LSTM_BYTES);
    cudaFuncSetAttribute(lstm_merged_kernel, cudaFuncAttributeMaxDynamicSharedMemorySize, SMEM_LSTM_BYTES);

    float *feat, *h1, *c1, *h2, *c2, *b1p, *b2p;
    uint32_t *W1h, *W2h;
    cudaGetSymbolAddress((void**)&feat, g_feat);
    cudaGetSymbolAddress((void**)&h1, g_h1);
    cudaGetSymbolAddress((void**)&c1, g_c1);
    cudaGetSymbolAddress((void**)&h2, g_h2);
    cudaGetSymbolAddress((void**)&c2, g_c2);
    cudaGetSymbolAddress((void**)&W1h, g_W1h);
    cudaGetSymbolAddress((void**)&W2h, g_W2h);
    cudaGetSymbolAddress((void**)&b1p, g_b1p);
    cudaGetSymbolAddress((void**)&b2p, g_b2p);

    const int prep_total = 12 * 8192 + 8 * 8192 + 1024 + 7168 + 32768;
    prep_kernel<<<(prep_total + 255) / 256, 256>>>(w_ih1, w_hh1, b_ih1, b_hh1,
                                                   w_ih2, w_hh2, b_ih2, b_hh2,
                                                   conv2_w, conv3_w);

    conv_kernel<<<Bn / 32, 256, CONV_SMEM_BYTES>>>(x, conv1_w, conv1_b, conv2_b, conv3_b);

    // L1_0: writes h1[0]
    lstm_single_kernel<<<1024, 256, SMEM_LSTM_BYTES>>>(
        feat, 128, 128, nullptr, 0, W1h, b1p, nullptr, h1, c1);

    // merged steps: launch s contains [L1_s | L2_{s-1}]
    for (int s = 1; s <= Tn; s++) {
        const float* A      = ps + (size_t)(s - 1) * Bn * 256;
        const float* h1prev = h1 + (size_t)((s - 1) & 1) * BH;
        float*       h1out  = h1 + (size_t)(s & 1) * BH;
        const float* h2old  = h2 + (size_t)(s & 1) * BH;        // h2_{s-2}, valid s>=2
        float*       h2out  = h2 + (size_t)((s - 1) & 1) * BH;  // h2_{s-1}
        lstm_merged_kernel<<<2048, 256, SMEM_LSTM_BYTES>>>(
            A, h1prev, W1h, b1p, c1, h1out, c1,
            (s >= 2) ? h2old : nullptr, head_w, head_b,
            (s >= 2) ? (out + (size_t)(s - 2) * Bn * 9) : nullptr,
            h1prev, (s >= 2) ? h2old : nullptr, (s >= 2) ? 128 : 0,
            W2h, b2p, (s >= 2) ? c2 : nullptr, h2out, c2);
    }

    // L2_16
    lstm_single_kernel<<<1024, 256, SMEM_LSTM_BYTES>>>(
        h1, 128, 128, h2 + BH, 128, W2h, b2p, c2, h2, c2);

    // heads for steps 15 and 16
    head2_kernel<<<1024, 256>>>(h2 + BH, h2, head_w, head_b,
                                out + (size_t)15 * Bn * 9, out + (size_t)16 * Bn * 9);
}